// round 1
// baseline (speedup 1.0000x reference)
#include <cuda_runtime.h>
#include <math.h>

#define BB 64
#define LD 512
#define LQ 128
#define DD 512

// ---------------- scratch (static device arrays; no allocation) ----------------
__device__ float g_self_d[(size_t)BB*LD*DD];
__device__ float g_self_q[(size_t)BB*LQ*DD];
__device__ float g_sdd[(size_t)BB*LD*DD];   // d_w * (d_node @ W_dd^T)
__device__ float g_sqd[(size_t)BB*LD*DD];   // d_w * (d_node @ W_qd^T)
__device__ float g_sqq[(size_t)BB*LQ*DD];   // q_w * (q_node @ W_qq^T)
__device__ float g_sdq[(size_t)BB*LQ*DD];   // q_w * (q_node @ W_dq^T)
__device__ float g_dcur[(size_t)BB*LD*DD];
__device__ float g_qcur[(size_t)BB*LQ*DD];
__device__ float g_dnb[BB*LD];              // 1 / clamped neighbor count
__device__ float g_qnb[BB*LQ];
__device__ float g_dw[BB*LD];
__device__ float g_qw[BB*LQ];

// ---------------- neighbor counts (inverse, clamped) ----------------
__global__ void nb_kernel(const int* __restrict__ A1, const int* __restrict__ A2,
                          int K1, int K2, int nrows, float* __restrict__ out) {
    int w = (blockIdx.x * blockDim.x + threadIdx.x) >> 5;
    int lane = threadIdx.x & 31;
    if (w >= nrows) return;
    const int* r1 = A1 + (size_t)w * K1;
    const int* r2 = A2 + (size_t)w * K2;
    int s = 0;
    for (int j = lane; j < K1; j += 32) s += r1[j];
    for (int j = lane; j < K2; j += 32) s += r2[j];
    #pragma unroll
    for (int o = 16; o; o >>= 1) s += __shfl_xor_sync(0xFFFFFFFFu, s, o);
    if (lane == 0) {
        float f = (s < 1) ? 1.0f : (float)s;
        out[w] = 1.0f / f;
    }
}

// ---------------- node weights: sigmoid(x . W_nw + b_nw) ----------------
__global__ void nw_kernel(const float* __restrict__ X, const float* __restrict__ Wnw,
                          const float* __restrict__ bnw,
                          float* __restrict__ wbuf, float* __restrict__ outw,
                          int nrows, int L, int stride_b) {
    int w = (blockIdx.x * blockDim.x + threadIdx.x) >> 5;
    int lane = threadIdx.x & 31;
    if (w >= nrows) return;
    const float* x = X + (size_t)w * DD;
    float s = 0.0f;
    #pragma unroll 4
    for (int j = lane; j < DD; j += 32) s += x[j] * Wnw[j];
    #pragma unroll
    for (int o = 16; o; o >>= 1) s += __shfl_xor_sync(0xFFFFFFFFu, s, o);
    if (lane == 0) {
        float z = s + bnw[0];
        float v = 1.0f / (1.0f + expf(-z));
        wbuf[w] = v;
        int b = w / L, l = w - b * L;
        outw[(size_t)b * stride_b + l] = v;
    }
}

// ---------------- weight GEMM: out[m, n] = (sum_k X[m,k]*W[n,k]) * rowscale[m] + bias[n] ----------------
// N = K = 512 fixed. 128x128 block tile, 8x8 per thread, Ktile=8.
__global__ void __launch_bounds__(256)
gemm_w(const float* __restrict__ X, const float* __restrict__ W,
       const float* __restrict__ bias, const float* __restrict__ rowscale,
       float* __restrict__ out) {
    __shared__ float As[8][132];
    __shared__ float Bs[8][132];
    int t = threadIdx.x;
    int r0 = blockIdx.y * 128;
    int c0 = blockIdx.x * 128;
    int lr = t >> 1;
    int lk = (t & 1) * 4;
    int tx = t & 15, ty = t >> 4;
    const float* Ap = X + (size_t)(r0 + lr) * DD + lk;
    const float* Bp = W + (size_t)(c0 + lr) * DD + lk;
    float acc[8][8];
    #pragma unroll
    for (int i = 0; i < 8; i++)
        #pragma unroll
        for (int j = 0; j < 8; j++) acc[i][j] = 0.0f;

    for (int kk = 0; kk < DD; kk += 8) {
        float4 a4 = *(const float4*)(Ap + kk);
        float4 b4 = *(const float4*)(Bp + kk);
        __syncthreads();
        As[lk + 0][lr] = a4.x; As[lk + 1][lr] = a4.y;
        As[lk + 2][lr] = a4.z; As[lk + 3][lr] = a4.w;
        Bs[lk + 0][lr] = b4.x; Bs[lk + 1][lr] = b4.y;
        Bs[lk + 2][lr] = b4.z; Bs[lk + 3][lr] = b4.w;
        __syncthreads();
        #pragma unroll
        for (int k = 0; k < 8; k++) {
            float4 a0 = *(const float4*)&As[k][ty * 8];
            float4 a1 = *(const float4*)&As[k][ty * 8 + 4];
            float4 bb0 = *(const float4*)&Bs[k][tx * 8];
            float4 bb1 = *(const float4*)&Bs[k][tx * 8 + 4];
            float av[8] = {a0.x, a0.y, a0.z, a0.w, a1.x, a1.y, a1.z, a1.w};
            float bv[8] = {bb0.x, bb0.y, bb0.z, bb0.w, bb1.x, bb1.y, bb1.z, bb1.w};
            #pragma unroll
            for (int i = 0; i < 8; i++)
                #pragma unroll
                for (int j = 0; j < 8; j++)
                    acc[i][j] += av[i] * bv[j];
        }
    }

    #pragma unroll
    for (int i = 0; i < 8; i++) {
        int r = r0 + ty * 8 + i;
        float sc = rowscale ? rowscale[r] : 1.0f;
        #pragma unroll
        for (int jj = 0; jj < 2; jj++) {
            int c = c0 + tx * 8 + jj * 4;
            float4 v;
            v.x = acc[i][jj * 4 + 0] * sc;
            v.y = acc[i][jj * 4 + 1] * sc;
            v.z = acc[i][jj * 4 + 2] * sc;
            v.w = acc[i][jj * 4 + 3] * sc;
            if (bias) {
                const float4 bz = *(const float4*)&bias[c];
                v.x += bz.x; v.y += bz.y; v.z += bz.z; v.w += bz.w;
            }
            *(float4*)&out[(size_t)r * DD + c] = v;
        }
    }
}

// ---------------- message GEMM with fused epilogue ----------------
// out[b,i,n] = relu(self[b,i,n] + invnb[b,i] * (A1[b]@B1[b] + A2[b]@B2[b])[i,n])
// A row-major int [M,K], B row-major float [K,512]. K1,K2 multiples of 8.
__global__ void __launch_bounds__(256)
gemm_msg(const int* __restrict__ A1, const int* __restrict__ A2, int K1, int K2,
         const float* __restrict__ B1, const float* __restrict__ B2,
         const float* __restrict__ selfb, const float* __restrict__ invnb,
         float* __restrict__ out, int M) {
    int b = blockIdx.z;
    A1 += (size_t)b * M * K1;
    A2 += (size_t)b * M * K2;
    B1 += (size_t)b * K1 * DD;
    B2 += (size_t)b * K2 * DD;
    selfb += (size_t)b * M * DD;
    invnb += (size_t)b * M;
    out += (size_t)b * M * DD;

    __shared__ float As[8][132];
    __shared__ float Bs[8][132];
    int t = threadIdx.x;
    int r0 = blockIdx.y * 128;
    int c0 = blockIdx.x * 128;
    int lrA = t >> 1;
    int lkA = (t & 1) * 4;
    int lkB = t >> 5;
    int lnB = (t & 31) * 4;
    int tx = t & 15, ty = t >> 4;

    float acc[8][8];
    #pragma unroll
    for (int i = 0; i < 8; i++)
        #pragma unroll
        for (int j = 0; j < 8; j++) acc[i][j] = 0.0f;

    int Ktot = K1 + K2;
    for (int kk = 0; kk < Ktot; kk += 8) {
        const int* Ap;
        const float* Bp;
        if (kk < K1) {
            Ap = A1 + (size_t)(r0 + lrA) * K1 + kk + lkA;
            Bp = B1 + (size_t)(kk + lkB) * DD + c0 + lnB;
        } else {
            int k2 = kk - K1;
            Ap = A2 + (size_t)(r0 + lrA) * K2 + k2 + lkA;
            Bp = B2 + (size_t)(k2 + lkB) * DD + c0 + lnB;
        }
        int4 ai = *(const int4*)Ap;
        float4 b4 = *(const float4*)Bp;
        __syncthreads();
        As[lkA + 0][lrA] = (float)ai.x;
        As[lkA + 1][lrA] = (float)ai.y;
        As[lkA + 2][lrA] = (float)ai.z;
        As[lkA + 3][lrA] = (float)ai.w;
        *(float4*)&Bs[lkB][lnB] = b4;
        __syncthreads();
        #pragma unroll
        for (int k = 0; k < 8; k++) {
            float4 a0 = *(const float4*)&As[k][ty * 8];
            float4 a1 = *(const float4*)&As[k][ty * 8 + 4];
            float4 bb0 = *(const float4*)&Bs[k][tx * 8];
            float4 bb1 = *(const float4*)&Bs[k][tx * 8 + 4];
            float av[8] = {a0.x, a0.y, a0.z, a0.w, a1.x, a1.y, a1.z, a1.w};
            float bv[8] = {bb0.x, bb0.y, bb0.z, bb0.w, bb1.x, bb1.y, bb1.z, bb1.w};
            #pragma unroll
            for (int i = 0; i < 8; i++)
                #pragma unroll
                for (int j = 0; j < 8; j++)
                    acc[i][j] += av[i] * bv[j];
        }
    }

    #pragma unroll
    for (int i = 0; i < 8; i++) {
        int r = r0 + ty * 8 + i;
        float inb = invnb[r];
        #pragma unroll
        for (int jj = 0; jj < 2; jj++) {
            int c = c0 + tx * 8 + jj * 4;
            const float4 s4 = *(const float4*)&selfb[(size_t)r * DD + c];
            float4 v;
            v.x = fmaxf(s4.x + acc[i][jj * 4 + 0] * inb, 0.0f);
            v.y = fmaxf(s4.y + acc[i][jj * 4 + 1] * inb, 0.0f);
            v.z = fmaxf(s4.z + acc[i][jj * 4 + 2] * inb, 0.0f);
            v.w = fmaxf(s4.w + acc[i][jj * 4 + 3] * inb, 0.0f);
            *(float4*)&out[(size_t)r * DD + c] = v;
        }
    }
}

// ---------------- host orchestration ----------------
extern "C" void kernel_launch(void* const* d_in, const int* in_sizes, int n_in,
                              void* d_out_, int out_size) {
    const float* d_node = (const float*)d_in[0];
    const float* q_node = (const float*)d_in[1];
    const int*   qq     = (const int*)d_in[2];
    const int*   dq     = (const int*)d_in[3];
    const int*   dd     = (const int*)d_in[4];
    const int*   qd     = (const int*)d_in[5];
    const float* W_nw   = (const float*)d_in[6];
    const float* b_nw   = (const float*)d_in[7];
    const float* W_self = (const float*)d_in[8];
    const float* b_self = (const float*)d_in[9];
    const float* W_dd   = (const float*)d_in[10];
    const float* W_qq   = (const float*)d_in[11];
    const float* W_dq   = (const float*)d_in[12];
    const float* W_qd   = (const float*)d_in[13];
    // d_in[14] = iteration_steps (always 2; dims hardcoded)

    float* out = (float*)d_out_;
    float* out_dnode = out;
    float* out_qnode = out + (size_t)BB * LD * DD;
    float* out_dw    = out_qnode + (size_t)BB * LQ * DD;
    float* out_qw    = out_dw + (size_t)BB * 2 * LD;

    float *p_self_d, *p_self_q, *p_sdd, *p_sqd, *p_sqq, *p_sdq;
    float *p_dcur, *p_qcur, *p_dnb, *p_qnb, *p_dw, *p_qw;
    cudaGetSymbolAddress((void**)&p_self_d, g_self_d);
    cudaGetSymbolAddress((void**)&p_self_q, g_self_q);
    cudaGetSymbolAddress((void**)&p_sdd, g_sdd);
    cudaGetSymbolAddress((void**)&p_sqd, g_sqd);
    cudaGetSymbolAddress((void**)&p_sqq, g_sqq);
    cudaGetSymbolAddress((void**)&p_sdq, g_sdq);
    cudaGetSymbolAddress((void**)&p_dcur, g_dcur);
    cudaGetSymbolAddress((void**)&p_qcur, g_qcur);
    cudaGetSymbolAddress((void**)&p_dnb, g_dnb);
    cudaGetSymbolAddress((void**)&p_qnb, g_qnb);
    cudaGetSymbolAddress((void**)&p_dw, g_dw);
    cudaGetSymbolAddress((void**)&p_qw, g_qw);

    // inverse neighbor counts (step-invariant)
    nb_kernel<<<BB * LD / 8, 256>>>(dd, dq, LD, LQ, BB * LD, p_dnb);
    nb_kernel<<<BB * LQ / 8, 256>>>(qq, qd, LQ, LD, BB * LQ, p_qnb);

    const float* Xd = d_node;
    const float* Xq = q_node;

    for (int t = 0; t < 2; t++) {
        bool last = (t == 1);

        // node weights (also writes all_d_w / all_q_w output slices)
        nw_kernel<<<BB * LD / 8, 256>>>(Xd, W_nw, b_nw, p_dw, out_dw + t * LD,
                                        BB * LD, LD, 2 * LD);
        nw_kernel<<<BB * LQ / 8, 256>>>(Xq, W_nw, b_nw, p_qw, out_qw + t * LQ,
                                        BB * LQ, LQ, 2 * LQ);

        // shared-weight GEMMs with fused bias / row-scale
        dim3 gd(4, BB * LD / 128);
        dim3 gq(4, BB * LQ / 128);
        gemm_w<<<gd, 256>>>(Xd, W_self, b_self, nullptr, p_self_d);
        gemm_w<<<gd, 256>>>(Xd, W_dd,   nullptr, p_dw,   p_sdd);
        gemm_w<<<gd, 256>>>(Xd, W_qd,   nullptr, p_dw,   p_sqd);
        gemm_w<<<gq, 256>>>(Xq, W_self, b_self, nullptr, p_self_q);
        gemm_w<<<gq, 256>>>(Xq, W_qq,   nullptr, p_qw,   p_sqq);
        gemm_w<<<gq, 256>>>(Xq, W_dq,   nullptr, p_qw,   p_sdq);

        // fused message GEMMs (dd|dq concat along K) + relu(self + agg/nb)
        float* outd = last ? out_dnode : p_dcur;
        float* outq = last ? out_qnode : p_qcur;
        gemm_msg<<<dim3(4, LD / 128, BB), 256>>>(dd, dq, LD, LQ, p_sdd, p_sdq,
                                                 p_self_d, p_dnb, outd, LD);
        gemm_msg<<<dim3(4, LQ / 128, BB), 256>>>(qq, qd, LQ, LD, p_sqq, p_sqd,
                                                 p_self_q, p_qnb, outq, LQ);
        Xd = outd;
        Xq = outq;
    }
    (void)in_sizes; (void)n_in; (void)out_size;
}

// round 3
// speedup vs baseline: 3.0294x; 3.0294x over previous
#include <cuda_runtime.h>
#include <math.h>
#include <stdint.h>

#define BB 64
#define LDN 512
#define LQN 128
#define DDIM 512
#define RS 36   // smem row stride in floats (pad 32->36 keeps 16B align, kills conflicts)

// ---------------- scratch (static device arrays; no allocation) ----------------
__device__ float g_self_d[(size_t)BB*LDN*DDIM];
__device__ float g_self_q[(size_t)BB*LQN*DDIM];
__device__ float g_sdd[(size_t)BB*DDIM*LDN];   // transposed: [b][n=512][j=Ld]
__device__ float g_sqd[(size_t)BB*DDIM*LDN];   // transposed: [b][n=512][j=Ld]
__device__ float g_sqq[(size_t)BB*DDIM*LQN];   // transposed: [b][n=512][j=Lq]
__device__ float g_sdq[(size_t)BB*DDIM*LQN];   // transposed: [b][n=512][j=Lq]
__device__ float g_dcur[(size_t)BB*LDN*DDIM];
__device__ float g_qcur[(size_t)BB*LQN*DDIM];
__device__ float g_dnb[BB*LDN];
__device__ float g_qnb[BB*LQN];
__device__ float g_dw[BB*LDN];
__device__ float g_qw[BB*LQN];

// ---------------- helpers ----------------
__device__ __forceinline__ float to_tf32(float x) {
    uint32_t u;
    asm("cvt.rna.tf32.f32 %0, %1;" : "=r"(u) : "f"(x));
    return __uint_as_float(u);
}
__device__ __forceinline__ void mma8(float* c, const uint32_t* a, const uint32_t* b) {
    asm volatile(
        "mma.sync.aligned.m16n8k8.row.col.f32.tf32.tf32.f32 "
        "{%0,%1,%2,%3}, {%4,%5,%6,%7}, {%8,%9}, {%0,%1,%2,%3};"
        : "+f"(c[0]), "+f"(c[1]), "+f"(c[2]), "+f"(c[3])
        : "r"(a[0]), "r"(a[1]), "r"(a[2]), "r"(a[3]), "r"(b[0]), "r"(b[1]));
}
__device__ __forceinline__ uint32_t fbits(float x) { return __float_as_uint(x); }

// ---------------- neighbor counts (inverse, clamped) ----------------
__global__ void nb_kernel(const int* __restrict__ A1, const int* __restrict__ A2,
                          int K1, int K2, int nrows, float* __restrict__ out) {
    int w = (blockIdx.x * blockDim.x + threadIdx.x) >> 5;
    int lane = threadIdx.x & 31;
    if (w >= nrows) return;
    const int* r1 = A1 + (size_t)w * K1;
    const int* r2 = A2 + (size_t)w * K2;
    int s = 0;
    for (int j = lane; j < K1; j += 32) s += r1[j];
    for (int j = lane; j < K2; j += 32) s += r2[j];
    #pragma unroll
    for (int o = 16; o; o >>= 1) s += __shfl_xor_sync(0xFFFFFFFFu, s, o);
    if (lane == 0) {
        float f = (s < 1) ? 1.0f : (float)s;
        out[w] = 1.0f / f;
    }
}

// ---------------- node weights: sigmoid(x . W_nw + b_nw) ----------------
__global__ void nw_kernel(const float* __restrict__ X, const float* __restrict__ Wnw,
                          const float* __restrict__ bnw,
                          float* __restrict__ wbuf, float* __restrict__ outw,
                          int nrows, int L, int stride_b) {
    int w = (blockIdx.x * blockDim.x + threadIdx.x) >> 5;
    int lane = threadIdx.x & 31;
    if (w >= nrows) return;
    const float* x = X + (size_t)w * DDIM;
    float s = 0.0f;
    #pragma unroll 4
    for (int j = lane; j < DDIM; j += 32) s += x[j] * Wnw[j];
    #pragma unroll
    for (int o = 16; o; o >>= 1) s += __shfl_xor_sync(0xFFFFFFFFu, s, o);
    if (lane == 0) {
        float z = s + bnw[0];
        float v = 1.0f / (1.0f + expf(-z));
        wbuf[w] = v;
        int b = w / L, l = w - b * L;
        outw[(size_t)b * stride_b + l] = v;
    }
}

// ---------------- tf32 mma.sync weight GEMM (3 weights fused in grid.x) ----------------
// widx = blockIdx.x>>2: 0 = self (bias, [r][c] store), 1/2 = info (rowscale, transposed)
__global__ void __launch_bounds__(256)
gemm_w_mma(const float* __restrict__ X,
           const float* __restrict__ W0, const float* __restrict__ W1,
           const float* __restrict__ W2,
           const float* __restrict__ bias, const float* __restrict__ rowscale,
           float* __restrict__ outS, float* __restrict__ outT1,
           float* __restrict__ outT2, int Lshift) {
    __shared__ float As[128 * RS];
    __shared__ float Bs[128 * RS];
    int t = threadIdx.x;
    int widx = blockIdx.x >> 2;
    int c0 = (blockIdx.x & 3) * 128;
    int r0 = blockIdx.y * 128;
    const float* W = (widx == 0) ? W0 : (widx == 1 ? W1 : W2);

    int lr = t >> 3;       // 0..31
    int lq = t & 7;        // 0..7
    const float* Ab = X + (size_t)(r0 + lr) * DDIM + lq * 4;
    const float* Bb = W + (size_t)(c0 + lr) * DDIM + lq * 4;

    int lane = t & 31, g = lane >> 2, tg = lane & 3;
    int wid = t >> 5, wy = wid & 1, wx = wid >> 1;

    float acc[4][4][4];
    #pragma unroll
    for (int i = 0; i < 4; i++)
        #pragma unroll
        for (int j = 0; j < 4; j++)
            #pragma unroll
            for (int k = 0; k < 4; k++) acc[i][j][k] = 0.0f;

    float4 Ar[4], Br[4];
    #pragma unroll
    for (int it = 0; it < 4; it++) {
        Ar[it] = *(const float4*)(Ab + (size_t)it * 32 * DDIM);
        Br[it] = *(const float4*)(Bb + (size_t)it * 32 * DDIM);
    }

    for (int c = 0; c < 16; c++) {
        // store staged chunk to smem (rna-convert once here)
        #pragma unroll
        for (int it = 0; it < 4; it++) {
            float4 va = Ar[it];
            va.x = to_tf32(va.x); va.y = to_tf32(va.y);
            va.z = to_tf32(va.z); va.w = to_tf32(va.w);
            *(float4*)&As[(lr + it * 32) * RS + lq * 4] = va;
            float4 vb = Br[it];
            vb.x = to_tf32(vb.x); vb.y = to_tf32(vb.y);
            vb.z = to_tf32(vb.z); vb.w = to_tf32(vb.w);
            *(float4*)&Bs[(lr + it * 32) * RS + lq * 4] = vb;
        }
        __syncthreads();
        if (c + 1 < 16) {
            int kk = (c + 1) * 32;
            #pragma unroll
            for (int it = 0; it < 4; it++) {
                Ar[it] = *(const float4*)(Ab + (size_t)it * 32 * DDIM + kk);
                Br[it] = *(const float4*)(Bb + (size_t)it * 32 * DDIM + kk);
            }
        }
        // compute 32-K chunk
        #pragma unroll
        for (int k8 = 0; k8 < 4; k8++) {
            int kb = k8 * 8;
            uint32_t a[4][4], b[4][2];
            #pragma unroll
            for (int i = 0; i < 4; i++) {
                int R = wy * 64 + i * 16 + g;
                a[i][0] = fbits(As[R * RS + kb + tg]);
                a[i][1] = fbits(As[(R + 8) * RS + kb + tg]);
                a[i][2] = fbits(As[R * RS + kb + 4 + tg]);
                a[i][3] = fbits(As[(R + 8) * RS + kb + 4 + tg]);
            }
            #pragma unroll
            for (int j = 0; j < 4; j++) {
                int C = wx * 32 + j * 8 + g;
                b[j][0] = fbits(Bs[C * RS + kb + tg]);
                b[j][1] = fbits(Bs[C * RS + kb + 4 + tg]);
            }
            #pragma unroll
            for (int i = 0; i < 4; i++)
                #pragma unroll
                for (int j = 0; j < 4; j++)
                    mma8(acc[i][j], a[i], b[j]);
        }
        __syncthreads();
    }

    // epilogue
    if (widx == 0) {
        #pragma unroll
        for (int i = 0; i < 4; i++) {
            int R0 = r0 + wy * 64 + i * 16 + g;
            #pragma unroll
            for (int j = 0; j < 4; j++) {
                int C = c0 + wx * 32 + j * 8 + 2 * tg;
                float2 bz = *(const float2*)&bias[C];
                float2 v0 = {acc[i][j][0] + bz.x, acc[i][j][1] + bz.y};
                *(float2*)&outS[(size_t)R0 * DDIM + C] = v0;
                float2 v1 = {acc[i][j][2] + bz.x, acc[i][j][3] + bz.y};
                *(float2*)&outS[(size_t)(R0 + 8) * DDIM + C] = v1;
            }
        }
    } else {
        float* ot = (widx == 1) ? outT1 : outT2;
        int L = 1 << Lshift, Lm = L - 1;
        #pragma unroll
        for (int i = 0; i < 4; i++) {
            int R0 = r0 + wy * 64 + i * 16 + g;
            int R1 = R0 + 8;
            float s0 = rowscale[R0], s1 = rowscale[R1];
            float* b0 = ot + ((size_t)(R0 >> Lshift) * DDIM) * L + (R0 & Lm);
            float* b1 = ot + ((size_t)(R1 >> Lshift) * DDIM) * L + (R1 & Lm);
            #pragma unroll
            for (int j = 0; j < 4; j++) {
                int C = c0 + wx * 32 + j * 8 + 2 * tg;
                b0[(size_t)C * L] = acc[i][j][0] * s0;
                b0[(size_t)(C + 1) * L] = acc[i][j][1] * s0;
                b1[(size_t)C * L] = acc[i][j][2] * s1;
                b1[(size_t)(C + 1) * L] = acc[i][j][3] * s1;
            }
        }
    }
}

// ---------------- tf32 mma.sync message GEMM ----------------
// out[b,i,n] = relu(self[b,i,n] + invnb[b,i] * (A1@B1^T + A2@B2^T)[i,n])
// A graphs int [M][K] K-major; B transposed info [512][K] K-major.
__global__ void __launch_bounds__(256)
gemm_msg_mma(const int* __restrict__ A1, int K1, const float* __restrict__ B1,
             const int* __restrict__ A2, int K2, const float* __restrict__ B2,
             const float* __restrict__ selfb, const float* __restrict__ invnb,
             float* __restrict__ out, int M) {
    int bz = blockIdx.z;
    A1 += (size_t)bz * M * K1;
    B1 += (size_t)bz * DDIM * K1;
    A2 += (size_t)bz * M * K2;
    B2 += (size_t)bz * DDIM * K2;
    selfb += (size_t)bz * M * DDIM;
    invnb += (size_t)bz * M;
    out += (size_t)bz * M * DDIM;

    __shared__ float As[128 * RS];
    __shared__ float Bs[128 * RS];
    int t = threadIdx.x;
    int c0 = blockIdx.x * 128;
    int r0 = blockIdx.y * 128;

    int lr = t >> 3, lq = t & 7;
    int lane = t & 31, g = lane >> 2, tg = lane & 3;
    int wid = t >> 5, wy = wid & 1, wx = wid >> 1;

    float acc[4][4][4];
    #pragma unroll
    for (int i = 0; i < 4; i++)
        #pragma unroll
        for (int j = 0; j < 4; j++)
            #pragma unroll
            for (int k = 0; k < 4; k++) acc[i][j][k] = 0.0f;

    int nch = (K1 + K2) >> 5;
    int4 Ai[4];
    float4 Br[4];
    // preload chunk 0 (always from source 1)
    {
        const int* Ap = A1 + (size_t)(r0 + lr) * K1 + lq * 4;
        const float* Bp = B1 + (size_t)(c0 + lr) * K1 + lq * 4;
        #pragma unroll
        for (int it = 0; it < 4; it++) {
            Ai[it] = *(const int4*)(Ap + (size_t)it * 32 * K1);
            Br[it] = *(const float4*)(Bp + (size_t)it * 32 * K1);
        }
    }

    for (int c = 0; c < nch; c++) {
        #pragma unroll
        for (int it = 0; it < 4; it++) {
            float4 va;
            va.x = (float)Ai[it].x; va.y = (float)Ai[it].y;
            va.z = (float)Ai[it].z; va.w = (float)Ai[it].w;
            *(float4*)&As[(lr + it * 32) * RS + lq * 4] = va;
            float4 vb = Br[it];
            vb.x = to_tf32(vb.x); vb.y = to_tf32(vb.y);
            vb.z = to_tf32(vb.z); vb.w = to_tf32(vb.w);
            *(float4*)&Bs[(lr + it * 32) * RS + lq * 4] = vb;
        }
        __syncthreads();
        if (c + 1 < nch) {
            int kk = (c + 1) * 32;
            if (kk < K1) {
                const int* Ap = A1 + (size_t)(r0 + lr) * K1 + kk + lq * 4;
                const float* Bp = B1 + (size_t)(c0 + lr) * K1 + kk + lq * 4;
                #pragma unroll
                for (int it = 0; it < 4; it++) {
                    Ai[it] = *(const int4*)(Ap + (size_t)it * 32 * K1);
                    Br[it] = *(const float4*)(Bp + (size_t)it * 32 * K1);
                }
            } else {
                int k2 = kk - K1;
                const int* Ap = A2 + (size_t)(r0 + lr) * K2 + k2 + lq * 4;
                const float* Bp = B2 + (size_t)(c0 + lr) * K2 + k2 + lq * 4;
                #pragma unroll
                for (int it = 0; it < 4; it++) {
                    Ai[it] = *(const int4*)(Ap + (size_t)it * 32 * K2);
                    Br[it] = *(const float4*)(Bp + (size_t)it * 32 * K2);
                }
            }
        }
        #pragma unroll
        for (int k8 = 0; k8 < 4; k8++) {
            int kb = k8 * 8;
            uint32_t a[4][4], b[4][2];
            #pragma unroll
            for (int i = 0; i < 4; i++) {
                int R = wy * 64 + i * 16 + g;
                a[i][0] = fbits(As[R * RS + kb + tg]);
                a[i][1] = fbits(As[(R + 8) * RS + kb + tg]);
                a[i][2] = fbits(As[R * RS + kb + 4 + tg]);
                a[i][3] = fbits(As[(R + 8) * RS + kb + 4 + tg]);
            }
            #pragma unroll
            for (int j = 0; j < 4; j++) {
                int C = wx * 32 + j * 8 + g;
                b[j][0] = fbits(Bs[C * RS + kb + tg]);
                b[j][1] = fbits(Bs[C * RS + kb + 4 + tg]);
            }
            #pragma unroll
            for (int i = 0; i < 4; i++)
                #pragma unroll
                for (int j = 0; j < 4; j++)
                    mma8(acc[i][j], a[i], b[j]);
        }
        __syncthreads();
    }

    // fused epilogue: relu(self + acc * invnb)
    #pragma unroll
    for (int i = 0; i < 4; i++) {
        int R0 = r0 + wy * 64 + i * 16 + g;
        int R1 = R0 + 8;
        float inv0 = invnb[R0], inv1 = invnb[R1];
        #pragma unroll
        for (int j = 0; j < 4; j++) {
            int C = c0 + wx * 32 + j * 8 + 2 * tg;
            float2 s0 = *(const float2*)&selfb[(size_t)R0 * DDIM + C];
            float2 v0;
            v0.x = fmaxf(s0.x + acc[i][j][0] * inv0, 0.0f);
            v0.y = fmaxf(s0.y + acc[i][j][1] * inv0, 0.0f);
            *(float2*)&out[(size_t)R0 * DDIM + C] = v0;
            float2 s1 = *(const float2*)&selfb[(size_t)R1 * DDIM + C];
            float2 v1;
            v1.x = fmaxf(s1.x + acc[i][j][2] * inv1, 0.0f);
            v1.y = fmaxf(s1.y + acc[i][j][3] * inv1, 0.0f);
            *(float2*)&out[(size_t)R1 * DDIM + C] = v1;
        }
    }
}

// ---------------- host orchestration ----------------
extern "C" void kernel_launch(void* const* d_in, const int* in_sizes, int n_in,
                              void* d_out_, int out_size) {
    const float* d_node = (const float*)d_in[0];
    const float* q_node = (const float*)d_in[1];
    const int*   qq     = (const int*)d_in[2];
    const int*   dq     = (const int*)d_in[3];
    const int*   dd     = (const int*)d_in[4];
    const int*   qd     = (const int*)d_in[5];
    const float* W_nw   = (const float*)d_in[6];
    const float* b_nw   = (const float*)d_in[7];
    const float* W_self = (const float*)d_in[8];
    const float* b_self = (const float*)d_in[9];
    const float* W_dd   = (const float*)d_in[10];
    const float* W_qq   = (const float*)d_in[11];
    const float* W_dq   = (const float*)d_in[12];
    const float* W_qd   = (const float*)d_in[13];

    float* out = (float*)d_out_;
    float* out_dnode = out;
    float* out_qnode = out + (size_t)BB * LDN * DDIM;
    float* out_dw    = out_qnode + (size_t)BB * LQN * DDIM;
    float* out_qw    = out_dw + (size_t)BB * 2 * LDN;

    float *p_self_d, *p_self_q, *p_sdd, *p_sqd, *p_sqq, *p_sdq;
    float *p_dcur, *p_qcur, *p_dnb, *p_qnb, *p_dw, *p_qw;
    cudaGetSymbolAddress((void**)&p_self_d, g_self_d);
    cudaGetSymbolAddress((void**)&p_self_q, g_self_q);
    cudaGetSymbolAddress((void**)&p_sdd, g_sdd);
    cudaGetSymbolAddress((void**)&p_sqd, g_sqd);
    cudaGetSymbolAddress((void**)&p_sqq, g_sqq);
    cudaGetSymbolAddress((void**)&p_sdq, g_sdq);
    cudaGetSymbolAddress((void**)&p_dcur, g_dcur);
    cudaGetSymbolAddress((void**)&p_qcur, g_qcur);
    cudaGetSymbolAddress((void**)&p_dnb, g_dnb);
    cudaGetSymbolAddress((void**)&p_qnb, g_qnb);
    cudaGetSymbolAddress((void**)&p_dw, g_dw);
    cudaGetSymbolAddress((void**)&p_qw, g_qw);

    nb_kernel<<<BB * LDN / 8, 256>>>(dd, dq, LDN, LQN, BB * LDN, p_dnb);
    nb_kernel<<<BB * LQN / 8, 256>>>(qq, qd, LQN, LDN, BB * LQN, p_qnb);

    const float* Xd = d_node;
    const float* Xq = q_node;

    for (int t = 0; t < 2; t++) {
        bool last = (t == 1);

        nw_kernel<<<BB * LDN / 8, 256>>>(Xd, W_nw, b_nw, p_dw, out_dw + t * LDN,
                                         BB * LDN, LDN, 2 * LDN);
        nw_kernel<<<BB * LQN / 8, 256>>>(Xq, W_nw, b_nw, p_qw, out_qw + t * LQN,
                                         BB * LQN, LQN, 2 * LQN);

        // fused 3-weight GEMMs (self normal, dd/qd and qq/dq transposed + rowscaled)
        gemm_w_mma<<<dim3(12, BB * LDN / 128), 256>>>(
            Xd, W_self, W_dd, W_qd, b_self, p_dw, p_self_d, p_sdd, p_sqd, 9);
        gemm_w_mma<<<dim3(12, BB * LQN / 128), 256>>>(
            Xq, W_self, W_qq, W_dq, b_self, p_qw, p_self_q, p_sqq, p_sdq, 7);

        float* outd = last ? out_dnode : p_dcur;
        float* outq = last ? out_qnode : p_qcur;
        gemm_msg_mma<<<dim3(4, LDN / 128, BB), 256>>>(
            dd, LDN, p_sdd, dq, LQN, p_sdq, p_self_d, p_dnb, outd, LDN);
        gemm_msg_mma<<<dim3(4, LQN / 128, BB), 256>>>(
            qq, LQN, p_sqq, qd, LDN, p_sqd, p_self_q, p_qnb, outq, LQN);
        Xd = outd;
        Xq = outq;
    }
    (void)in_sizes; (void)n_in; (void)out_size;
}

// round 4
// speedup vs baseline: 3.7353x; 1.2330x over previous
#include <cuda_runtime.h>
#include <math.h>
#include <stdint.h>

#define BB 64
#define LDN 512
#define LQN 128
#define DDIM 512
#define RSH 20   // smem row stride in half2 (uint) units: 16 data + 4 pad -> conflict-free frags

// ---------------- scratch (static device arrays; no allocation) ----------------
__device__ float g_self_d[(size_t)BB*LDN*DDIM];
__device__ float g_self_q[(size_t)BB*LQN*DDIM];
__device__ float g_sdd[(size_t)BB*DDIM*LDN];   // transposed: [b][n=512][j=Ld]
__device__ float g_sqd[(size_t)BB*DDIM*LDN];   // transposed: [b][n=512][j=Ld]
__device__ float g_sqq[(size_t)BB*DDIM*LQN];   // transposed: [b][n=512][j=Lq]
__device__ float g_sdq[(size_t)BB*DDIM*LQN];   // transposed: [b][n=512][j=Lq]
__device__ float g_dcur[(size_t)BB*LDN*DDIM];
__device__ float g_qcur[(size_t)BB*LQN*DDIM];
__device__ float g_dnb[BB*LDN];
__device__ float g_qnb[BB*LQN];
__device__ float g_dw[BB*LDN];
__device__ float g_qw[BB*LQN];

// ---------------- helpers ----------------
__device__ __forceinline__ uint32_t pk(float lo, float hi) {
    uint32_t u;
    asm("cvt.rn.f16x2.f32 %0, %1, %2;" : "=r"(u) : "f"(hi), "f"(lo));
    return u;
}
__device__ __forceinline__ void mma16(float* c, const uint32_t* a, const uint32_t* b) {
    asm volatile(
        "mma.sync.aligned.m16n8k16.row.col.f32.f16.f16.f32 "
        "{%0,%1,%2,%3}, {%4,%5,%6,%7}, {%8,%9}, {%0,%1,%2,%3};"
        : "+f"(c[0]), "+f"(c[1]), "+f"(c[2]), "+f"(c[3])
        : "r"(a[0]), "r"(a[1]), "r"(a[2]), "r"(a[3]), "r"(b[0]), "r"(b[1]));
}

// ---------------- neighbor counts (inverse, clamped) ----------------
__global__ void nb_kernel(const int* __restrict__ A1, const int* __restrict__ A2,
                          int K1, int K2, int nrows, float* __restrict__ out) {
    int w = (blockIdx.x * blockDim.x + threadIdx.x) >> 5;
    int lane = threadIdx.x & 31;
    if (w >= nrows) return;
    const int* r1 = A1 + (size_t)w * K1;
    const int* r2 = A2 + (size_t)w * K2;
    int s = 0;
    for (int j = lane; j < K1; j += 32) s += r1[j];
    for (int j = lane; j < K2; j += 32) s += r2[j];
    #pragma unroll
    for (int o = 16; o; o >>= 1) s += __shfl_xor_sync(0xFFFFFFFFu, s, o);
    if (lane == 0) {
        float f = (s < 1) ? 1.0f : (float)s;
        out[w] = 1.0f / f;
    }
}

// ---------------- node weights: sigmoid(x . W_nw + b_nw) ----------------
__global__ void nw_kernel(const float* __restrict__ X, const float* __restrict__ Wnw,
                          const float* __restrict__ bnw,
                          float* __restrict__ wbuf, float* __restrict__ outw,
                          int nrows, int L, int stride_b) {
    int w = (blockIdx.x * blockDim.x + threadIdx.x) >> 5;
    int lane = threadIdx.x & 31;
    if (w >= nrows) return;
    const float* x = X + (size_t)w * DDIM;
    float s = 0.0f;
    #pragma unroll 4
    for (int j = lane; j < DDIM; j += 32) s += x[j] * Wnw[j];
    #pragma unroll
    for (int o = 16; o; o >>= 1) s += __shfl_xor_sync(0xFFFFFFFFu, s, o);
    if (lane == 0) {
        float z = s + bnw[0];
        float v = 1.0f / (1.0f + expf(-z));
        wbuf[w] = v;
        int b = w / L, l = w - b * L;
        outw[(size_t)b * stride_b + l] = v;
    }
}

// ---------------- fp16 mma.sync weight GEMM (3 weights fused in grid.x) ----------------
// widx = blockIdx.x>>2: 0 = self (bias, [r][c] store), 1/2 = info (rowscale, transposed)
__global__ void __launch_bounds__(256)
gemm_w_mma(const float* __restrict__ X,
           const float* __restrict__ W0, const float* __restrict__ W1,
           const float* __restrict__ W2,
           const float* __restrict__ bias, const float* __restrict__ rowscale,
           float* __restrict__ outS, float* __restrict__ outT1,
           float* __restrict__ outT2, int Lshift) {
    __shared__ uint32_t As[128 * RSH];
    __shared__ uint32_t Bs[128 * RSH];
    int t = threadIdx.x;
    int widx = blockIdx.x >> 2;
    int c0 = (blockIdx.x & 3) * 128;
    int r0 = blockIdx.y * 128;
    const float* W = (widx == 0) ? W0 : (widx == 1 ? W1 : W2);

    int lr = t >> 3;       // 0..31
    int lq = t & 7;        // 0..7
    const float* Ab = X + (size_t)(r0 + lr) * DDIM + lq * 4;
    const float* Bb = W + (size_t)(c0 + lr) * DDIM + lq * 4;

    int lane = t & 31, g = lane >> 2, tg = lane & 3;
    int wid = t >> 5, wy = wid & 1, wx = wid >> 1;

    float acc[4][4][4];
    #pragma unroll
    for (int i = 0; i < 4; i++)
        #pragma unroll
        for (int j = 0; j < 4; j++)
            #pragma unroll
            for (int k = 0; k < 4; k++) acc[i][j][k] = 0.0f;

    float4 Ar[4], Br[4];
    #pragma unroll
    for (int it = 0; it < 4; it++) {
        Ar[it] = *(const float4*)(Ab + (size_t)it * 32 * DDIM);
        Br[it] = *(const float4*)(Bb + (size_t)it * 32 * DDIM);
    }

    for (int c = 0; c < 16; c++) {
        // store staged chunk to smem as fp16 (rn convert once here)
        #pragma unroll
        for (int it = 0; it < 4; it++) {
            uint2 pa = {pk(Ar[it].x, Ar[it].y), pk(Ar[it].z, Ar[it].w)};
            *(uint2*)&As[(lr + it * 32) * RSH + lq * 2] = pa;
            uint2 pb = {pk(Br[it].x, Br[it].y), pk(Br[it].z, Br[it].w)};
            *(uint2*)&Bs[(lr + it * 32) * RSH + lq * 2] = pb;
        }
        __syncthreads();
        if (c + 1 < 16) {
            int kk = (c + 1) * 32;
            #pragma unroll
            for (int it = 0; it < 4; it++) {
                Ar[it] = *(const float4*)(Ab + (size_t)it * 32 * DDIM + kk);
                Br[it] = *(const float4*)(Bb + (size_t)it * 32 * DDIM + kk);
            }
        }
        // compute 32-K chunk = 2 x k16
        #pragma unroll
        for (int k16 = 0; k16 < 2; k16++) {
            int kb = k16 * 8;
            uint32_t a[4][4], b[4][2];
            #pragma unroll
            for (int i = 0; i < 4; i++) {
                int R = wy * 64 + i * 16 + g;
                a[i][0] = As[R * RSH + kb + tg];
                a[i][1] = As[(R + 8) * RSH + kb + tg];
                a[i][2] = As[R * RSH + kb + tg + 4];
                a[i][3] = As[(R + 8) * RSH + kb + tg + 4];
            }
            #pragma unroll
            for (int j = 0; j < 4; j++) {
                int C = wx * 32 + j * 8 + g;
                b[j][0] = Bs[C * RSH + kb + tg];
                b[j][1] = Bs[C * RSH + kb + tg + 4];
            }
            #pragma unroll
            for (int i = 0; i < 4; i++)
                #pragma unroll
                for (int j = 0; j < 4; j++)
                    mma16(acc[i][j], a[i], b[j]);
        }
        __syncthreads();
    }

    // epilogue
    if (widx == 0) {
        #pragma unroll
        for (int i = 0; i < 4; i++) {
            int R0 = r0 + wy * 64 + i * 16 + g;
            #pragma unroll
            for (int j = 0; j < 4; j++) {
                int C = c0 + wx * 32 + j * 8 + 2 * tg;
                float2 bz = *(const float2*)&bias[C];
                float2 v0 = {acc[i][j][0] + bz.x, acc[i][j][1] + bz.y};
                *(float2*)&outS[(size_t)R0 * DDIM + C] = v0;
                float2 v1 = {acc[i][j][2] + bz.x, acc[i][j][3] + bz.y};
                *(float2*)&outS[(size_t)(R0 + 8) * DDIM + C] = v1;
            }
        }
    } else {
        float* ot = (widx == 1) ? outT1 : outT2;
        int L = 1 << Lshift, Lm = L - 1;
        #pragma unroll
        for (int i = 0; i < 4; i++) {
            int R0 = r0 + wy * 64 + i * 16 + g;
            int R1 = R0 + 8;
            float s0 = rowscale[R0], s1 = rowscale[R1];
            float* b0 = ot + ((size_t)(R0 >> Lshift) * DDIM) * L + (R0 & Lm);
            float* b1 = ot + ((size_t)(R1 >> Lshift) * DDIM) * L + (R1 & Lm);
            #pragma unroll
            for (int j = 0; j < 4; j++) {
                int C = c0 + wx * 32 + j * 8 + 2 * tg;
                b0[(size_t)C * L] = acc[i][j][0] * s0;
                b0[(size_t)(C + 1) * L] = acc[i][j][1] * s0;
                b1[(size_t)C * L] = acc[i][j][2] * s1;
                b1[(size_t)(C + 1) * L] = acc[i][j][3] * s1;
            }
        }
    }
}

// ---------------- fp16 mma.sync message GEMM ----------------
// out[b,i,n] = relu(self[b,i,n] + invnb[b,i] * (A1@B1^T + A2@B2^T)[i,n])
// A graphs int [M][K] K-major; B transposed info [512][K] K-major.
__global__ void __launch_bounds__(256)
gemm_msg_mma(const int* __restrict__ A1, int K1, const float* __restrict__ B1,
             const int* __restrict__ A2, int K2, const float* __restrict__ B2,
             const float* __restrict__ selfb, const float* __restrict__ invnb,
             float* __restrict__ out, int M) {
    int bz = blockIdx.z;
    A1 += (size_t)bz * M * K1;
    B1 += (size_t)bz * DDIM * K1;
    A2 += (size_t)bz * M * K2;
    B2 += (size_t)bz * DDIM * K2;
    selfb += (size_t)bz * M * DDIM;
    invnb += (size_t)bz * M;
    out += (size_t)bz * M * DDIM;

    __shared__ uint32_t As[128 * RSH];
    __shared__ uint32_t Bs[128 * RSH];
    int t = threadIdx.x;
    int c0 = blockIdx.x * 128;
    int r0 = blockIdx.y * 128;

    int lr = t >> 3, lq = t & 7;
    int lane = t & 31, g = lane >> 2, tg = lane & 3;
    int wid = t >> 5, wy = wid & 1, wx = wid >> 1;

    float acc[4][4][4];
    #pragma unroll
    for (int i = 0; i < 4; i++)
        #pragma unroll
        for (int j = 0; j < 4; j++)
            #pragma unroll
            for (int k = 0; k < 4; k++) acc[i][j][k] = 0.0f;

    int nch = (K1 + K2) >> 5;
    int4 Ai[4];
    float4 Br[4];
    // preload chunk 0 (always from source 1)
    {
        const int* Ap = A1 + (size_t)(r0 + lr) * K1 + lq * 4;
        const float* Bp = B1 + (size_t)(c0 + lr) * K1 + lq * 4;
        #pragma unroll
        for (int it = 0; it < 4; it++) {
            Ai[it] = *(const int4*)(Ap + (size_t)it * 32 * K1);
            Br[it] = *(const float4*)(Bp + (size_t)it * 32 * K1);
        }
    }

    for (int c = 0; c < nch; c++) {
        #pragma unroll
        for (int it = 0; it < 4; it++) {
            uint2 pa = {pk((float)Ai[it].x, (float)Ai[it].y),
                        pk((float)Ai[it].z, (float)Ai[it].w)};
            *(uint2*)&As[(lr + it * 32) * RSH + lq * 2] = pa;
            uint2 pb = {pk(Br[it].x, Br[it].y), pk(Br[it].z, Br[it].w)};
            *(uint2*)&Bs[(lr + it * 32) * RSH + lq * 2] = pb;
        }
        __syncthreads();
        if (c + 1 < nch) {
            int kk = (c + 1) * 32;
            if (kk < K1) {
                const int* Ap = A1 + (size_t)(r0 + lr) * K1 + kk + lq * 4;
                const float* Bp = B1 + (size_t)(c0 + lr) * K1 + kk + lq * 4;
                #pragma unroll
                for (int it = 0; it < 4; it++) {
                    Ai[it] = *(const int4*)(Ap + (size_t)it * 32 * K1);
                    Br[it] = *(const float4*)(Bp + (size_t)it * 32 * K1);
                }
            } else {
                int k2 = kk - K1;
                const int* Ap = A2 + (size_t)(r0 + lr) * K2 + k2 + lq * 4;
                const float* Bp = B2 + (size_t)(c0 + lr) * K2 + k2 + lq * 4;
                #pragma unroll
                for (int it = 0; it < 4; it++) {
                    Ai[it] = *(const int4*)(Ap + (size_t)it * 32 * K2);
                    Br[it] = *(const float4*)(Bp + (size_t)it * 32 * K2);
                }
            }
        }
        #pragma unroll
        for (int k16 = 0; k16 < 2; k16++) {
            int kb = k16 * 8;
            uint32_t a[4][4], b[4][2];
            #pragma unroll
            for (int i = 0; i < 4; i++) {
                int R = wy * 64 + i * 16 + g;
                a[i][0] = As[R * RSH + kb + tg];
                a[i][1] = As[(R + 8) * RSH + kb + tg];
                a[i][2] = As[R * RSH + kb + tg + 4];
                a[i][3] = As[(R + 8) * RSH + kb + tg + 4];
            }
            #pragma unroll
            for (int j = 0; j < 4; j++) {
                int C = wx * 32 + j * 8 + g;
                b[j][0] = Bs[C * RSH + kb + tg];
                b[j][1] = Bs[C * RSH + kb + tg + 4];
            }
            #pragma unroll
            for (int i = 0; i < 4; i++)
                #pragma unroll
                for (int j = 0; j < 4; j++)
                    mma16(acc[i][j], a[i], b[j]);
        }
        __syncthreads();
    }

    // fused epilogue: relu(self + acc * invnb)
    #pragma unroll
    for (int i = 0; i < 4; i++) {
        int R0 = r0 + wy * 64 + i * 16 + g;
        int R1 = R0 + 8;
        float inv0 = invnb[R0], inv1 = invnb[R1];
        #pragma unroll
        for (int j = 0; j < 4; j++) {
            int C = c0 + wx * 32 + j * 8 + 2 * tg;
            float2 s0 = *(const float2*)&selfb[(size_t)R0 * DDIM + C];
            float2 v0;
            v0.x = fmaxf(s0.x + acc[i][j][0] * inv0, 0.0f);
            v0.y = fmaxf(s0.y + acc[i][j][1] * inv0, 0.0f);
            *(float2*)&out[(size_t)R0 * DDIM + C] = v0;
            float2 s1 = *(const float2*)&selfb[(size_t)R1 * DDIM + C];
            float2 v1;
            v1.x = fmaxf(s1.x + acc[i][j][2] * inv1, 0.0f);
            v1.y = fmaxf(s1.y + acc[i][j][3] * inv1, 0.0f);
            *(float2*)&out[(size_t)R1 * DDIM + C] = v1;
        }
    }
}

// ---------------- host orchestration ----------------
extern "C" void kernel_launch(void* const* d_in, const int* in_sizes, int n_in,
                              void* d_out_, int out_size) {
    const float* d_node = (const float*)d_in[0];
    const float* q_node = (const float*)d_in[1];
    const int*   qq     = (const int*)d_in[2];
    const int*   dq     = (const int*)d_in[3];
    const int*   dd     = (const int*)d_in[4];
    const int*   qd     = (const int*)d_in[5];
    const float* W_nw   = (const float*)d_in[6];
    const float* b_nw   = (const float*)d_in[7];
    const float* W_self = (const float*)d_in[8];
    const float* b_self = (const float*)d_in[9];
    const float* W_dd   = (const float*)d_in[10];
    const float* W_qq   = (const float*)d_in[11];
    const float* W_dq   = (const float*)d_in[12];
    const float* W_qd   = (const float*)d_in[13];

    float* out = (float*)d_out_;
    float* out_dnode = out;
    float* out_qnode = out + (size_t)BB * LDN * DDIM;
    float* out_dw    = out_qnode + (size_t)BB * LQN * DDIM;
    float* out_qw    = out_dw + (size_t)BB * 2 * LDN;

    float *p_self_d, *p_self_q, *p_sdd, *p_sqd, *p_sqq, *p_sdq;
    float *p_dcur, *p_qcur, *p_dnb, *p_qnb, *p_dw, *p_qw;
    cudaGetSymbolAddress((void**)&p_self_d, g_self_d);
    cudaGetSymbolAddress((void**)&p_self_q, g_self_q);
    cudaGetSymbolAddress((void**)&p_sdd, g_sdd);
    cudaGetSymbolAddress((void**)&p_sqd, g_sqd);
    cudaGetSymbolAddress((void**)&p_sqq, g_sqq);
    cudaGetSymbolAddress((void**)&p_sdq, g_sdq);
    cudaGetSymbolAddress((void**)&p_dcur, g_dcur);
    cudaGetSymbolAddress((void**)&p_qcur, g_qcur);
    cudaGetSymbolAddress((void**)&p_dnb, g_dnb);
    cudaGetSymbolAddress((void**)&p_qnb, g_qnb);
    cudaGetSymbolAddress((void**)&p_dw, g_dw);
    cudaGetSymbolAddress((void**)&p_qw, g_qw);

    nb_kernel<<<BB * LDN / 8, 256>>>(dd, dq, LDN, LQN, BB * LDN, p_dnb);
    nb_kernel<<<BB * LQN / 8, 256>>>(qq, qd, LQN, LDN, BB * LQN, p_qnb);

    const float* Xd = d_node;
    const float* Xq = q_node;

    for (int t = 0; t < 2; t++) {
        bool last = (t == 1);

        nw_kernel<<<BB * LDN / 8, 256>>>(Xd, W_nw, b_nw, p_dw, out_dw + t * LDN,
                                         BB * LDN, LDN, 2 * LDN);
        nw_kernel<<<BB * LQN / 8, 256>>>(Xq, W_nw, b_nw, p_qw, out_qw + t * LQN,
                                         BB * LQN, LQN, 2 * LQN);

        // fused 3-weight GEMMs (self normal, dd/qd and qq/dq transposed + rowscaled)
        gemm_w_mma<<<dim3(12, BB * LDN / 128), 256>>>(
            Xd, W_self, W_dd, W_qd, b_self, p_dw, p_self_d, p_sdd, p_sqd, 9);
        gemm_w_mma<<<dim3(12, BB * LQN / 128), 256>>>(
            Xq, W_self, W_qq, W_dq, b_self, p_qw, p_self_q, p_sqq, p_sdq, 7);

        float* outd = last ? out_dnode : p_dcur;
        float* outq = last ? out_qnode : p_qcur;
        gemm_msg_mma<<<dim3(4, LDN / 128, BB), 256>>>(
            dd, LDN, p_sdd, dq, LQN, p_sdq, p_self_d, p_dnb, outd, LDN);
        gemm_msg_mma<<<dim3(4, LQN / 128, BB), 256>>>(
            qq, LQN, p_sqq, qd, LDN, p_sqd, p_self_q, p_qnb, outq, LQN);
        Xd = outd;
        Xq = outq;
    }
    (void)in_sizes; (void)n_in; (void)out_size;
}

// round 5
// speedup vs baseline: 4.5102x; 1.2074x over previous
#include <cuda_runtime.h>
#include <math.h>
#include <stdint.h>

#define BB 64
#define LDN 512
#define LQN 128
#define DDIM 512
#define KU   (DDIM/2)   // 256 uints (half2) per feature row
#define RSH  20         // smem row stride in uints: 16 data + 4 pad (conflict-free frags)

// ---------------- fp32 state ----------------
__device__ float g_self_d[(size_t)BB*LDN*DDIM];
__device__ float g_self_q[(size_t)BB*LQN*DDIM];
__device__ float g_dcur[(size_t)BB*LDN*DDIM];
__device__ float g_qcur[(size_t)BB*LQN*DDIM];
__device__ float g_dnb[BB*LDN];
__device__ float g_qnb[BB*LQN];
__device__ float g_dw[BB*LDN];
__device__ float g_qw[BB*LQN];
// ---------------- fp16 buffers (uint32 = half2, pairs along K) ----------------
__device__ uint32_t g_xdh[(size_t)BB*LDN*KU];
__device__ uint32_t g_xqh[(size_t)BB*LQN*KU];
__device__ uint32_t g_ddh[(size_t)BB*LDN*(LDN/2)];
__device__ uint32_t g_dqh[(size_t)BB*LDN*(LQN/2)];
__device__ uint32_t g_qqh[(size_t)BB*LQN*(LQN/2)];
__device__ uint32_t g_qdh[(size_t)BB*LQN*(LDN/2)];
__device__ uint32_t g_sddh[(size_t)BB*DDIM*(LDN/2)];  // [b][n][j] pairs along j
__device__ uint32_t g_sqdh[(size_t)BB*DDIM*(LDN/2)];
__device__ uint32_t g_sqqh[(size_t)BB*DDIM*(LQN/2)];
__device__ uint32_t g_sdqh[(size_t)BB*DDIM*(LQN/2)];
__device__ uint32_t g_wh[5][(size_t)DDIM*KU];         // self, dd, qd, qq, dq

// ---------------- helpers ----------------
__device__ __forceinline__ uint32_t pk(float lo, float hi) {
    uint32_t u;
    asm("cvt.rn.f16x2.f32 %0, %1, %2;" : "=r"(u) : "f"(hi), "f"(lo));
    return u;
}
__device__ __forceinline__ void mma16(float* c, const uint32_t* a, const uint32_t* b) {
    asm volatile(
        "mma.sync.aligned.m16n8k16.row.col.f32.f16.f16.f32 "
        "{%0,%1,%2,%3}, {%4,%5,%6,%7}, {%8,%9}, {%0,%1,%2,%3};"
        : "+f"(c[0]), "+f"(c[1]), "+f"(c[2]), "+f"(c[3])
        : "r"(a[0]), "r"(a[1]), "r"(a[2]), "r"(a[3]), "r"(b[0]), "r"(b[1]));
}
__device__ __forceinline__ uint32_t smem_u32(const void* p) {
    uint32_t a;
    asm("{ .reg .u64 t; cvta.to.shared.u64 t, %1; cvt.u32.u64 %0, t; }" : "=r"(a) : "l"(p));
    return a;
}
__device__ __forceinline__ void cp16(uint32_t daddr, const uint32_t* g) {
    asm volatile("cp.async.cg.shared.global [%0], [%1], 16;"
                 :: "r"(daddr), "l"(__cvta_generic_to_global((void*)g)));
}
__device__ __forceinline__ void cpcommit() { asm volatile("cp.async.commit_group;"); }
__device__ __forceinline__ void cpwait0()  { asm volatile("cp.async.wait_group 0;"); }
__device__ __forceinline__ void cpwait1()  { asm volatile("cp.async.wait_group 1;"); }

// stage one 128x32half tile pair (A,B) into buf via cp.async; 2x16B per thread per operand
__device__ __forceinline__ void issue2(uint32_t sb, int buf,
                                       const uint32_t* Asrc, int sA,
                                       const uint32_t* Bsrc, int sB,
                                       int kkU, int t) {
    #pragma unroll
    for (int s = 0; s < 2; s++) {
        int idx = t * 2 + s, row = idx >> 2, c4 = idx & 3;
        uint32_t off = (uint32_t)((row * RSH + c4 * 4) * 4);
        cp16(sb + (uint32_t)(buf * 2 + 0) * 10240u + off, Asrc + (size_t)row * sA + kkU + c4 * 4);
        cp16(sb + (uint32_t)(buf * 2 + 1) * 10240u + off, Bsrc + (size_t)row * sB + kkU + c4 * 4);
    }
    cpcommit();
}

__device__ __forceinline__ void compute_chunk(const uint32_t* As, const uint32_t* Bs,
                                              float acc[4][4][4],
                                              int g, int tg, int wy, int wx) {
    #pragma unroll
    for (int k16 = 0; k16 < 2; k16++) {
        int kb = k16 * 8;
        uint32_t a[4][4], b[4][2];
        #pragma unroll
        for (int i = 0; i < 4; i++) {
            int R = wy * 64 + i * 16 + g;
            a[i][0] = As[R * RSH + kb + tg];
            a[i][1] = As[(R + 8) * RSH + kb + tg];
            a[i][2] = As[R * RSH + kb + tg + 4];
            a[i][3] = As[(R + 8) * RSH + kb + tg + 4];
        }
        #pragma unroll
        for (int j = 0; j < 4; j++) {
            int C = wx * 32 + j * 8 + g;
            b[j][0] = Bs[C * RSH + kb + tg];
            b[j][1] = Bs[C * RSH + kb + tg + 4];
        }
        #pragma unroll
        for (int i = 0; i < 4; i++)
            #pragma unroll
            for (int j = 0; j < 4; j++)
                mma16(acc[i][j], a[i], b[j]);
    }
}

// ---------------- conversion kernels ----------------
__global__ void cvt_f2h(const float* __restrict__ s, uint32_t* __restrict__ d, int n4) {
    int i = blockIdx.x * blockDim.x + threadIdx.x;
    int st = gridDim.x * blockDim.x;
    for (; i < n4; i += st) {
        float4 v = *(const float4*)(s + (size_t)i * 4);
        uint2 o = {pk(v.x, v.y), pk(v.z, v.w)};
        *(uint2*)(d + (size_t)i * 2) = o;
    }
}
__global__ void cvt_i2h(const int* __restrict__ s, uint32_t* __restrict__ d, int n4) {
    int i = blockIdx.x * blockDim.x + threadIdx.x;
    int st = gridDim.x * blockDim.x;
    for (; i < n4; i += st) {
        int4 v = *(const int4*)(s + (size_t)i * 4);
        uint2 o = {pk((float)v.x, (float)v.y), pk((float)v.z, (float)v.w)};
        *(uint2*)(d + (size_t)i * 2) = o;
    }
}
__global__ void cvt_w(const float* __restrict__ w0, const float* __restrict__ w1,
                      const float* __restrict__ w2, const float* __restrict__ w3,
                      const float* __restrict__ w4, uint32_t* __restrict__ dst) {
    int i = blockIdx.x * blockDim.x + threadIdx.x;
    int st = gridDim.x * blockDim.x;
    for (; i < 5 * 65536; i += st) {
        int which = i >> 16, off = i & 65535;
        const float* w = which == 0 ? w0 : which == 1 ? w1 : which == 2 ? w2
                       : which == 3 ? w3 : w4;
        float4 v = *(const float4*)(w + (size_t)off * 4);
        uint2 o = {pk(v.x, v.y), pk(v.z, v.w)};
        *(uint2*)(dst + (size_t)i * 2) = o;
    }
}

// ---------------- neighbor counts (inverse, clamped) ----------------
__global__ void nb_kernel(const int* __restrict__ A1, const int* __restrict__ A2,
                          int K1, int K2, int nrows, float* __restrict__ out) {
    int w = (blockIdx.x * blockDim.x + threadIdx.x) >> 5;
    int lane = threadIdx.x & 31;
    if (w >= nrows) return;
    const int* r1 = A1 + (size_t)w * K1;
    const int* r2 = A2 + (size_t)w * K2;
    int s = 0;
    for (int j = lane; j < K1; j += 32) s += r1[j];
    for (int j = lane; j < K2; j += 32) s += r2[j];
    #pragma unroll
    for (int o = 16; o; o >>= 1) s += __shfl_xor_sync(0xFFFFFFFFu, s, o);
    if (lane == 0) {
        float f = (s < 1) ? 1.0f : (float)s;
        out[w] = 1.0f / f;
    }
}

// ---------------- node weights: sigmoid(x . W_nw + b_nw) ----------------
__global__ void nw_kernel(const float* __restrict__ X, const float* __restrict__ Wnw,
                          const float* __restrict__ bnw,
                          float* __restrict__ wbuf, float* __restrict__ outw,
                          int nrows, int L, int stride_b) {
    int w = (blockIdx.x * blockDim.x + threadIdx.x) >> 5;
    int lane = threadIdx.x & 31;
    if (w >= nrows) return;
    const float* x = X + (size_t)w * DDIM;
    float s = 0.0f;
    #pragma unroll 4
    for (int j = lane; j < DDIM; j += 32) s += x[j] * Wnw[j];
    #pragma unroll
    for (int o = 16; o; o >>= 1) s += __shfl_xor_sync(0xFFFFFFFFu, s, o);
    if (lane == 0) {
        float z = s + bnw[0];
        float v = 1.0f / (1.0f + expf(-z));
        wbuf[w] = v;
        int b = w / L, l = w - b * L;
        outw[(size_t)b * stride_b + l] = v;
    }
}

// ---------------- self GEMM: out[i][n] = X[i] . Wself[n] + bias[n] ----------------
__global__ void __launch_bounds__(256)
gemm_self(const uint32_t* __restrict__ Xh, const uint32_t* __restrict__ Wh,
          const float* __restrict__ bias, float* __restrict__ outS) {
    __shared__ uint32_t sm[2][2][2560];
    uint32_t sb = smem_u32(&sm[0][0][0]);
    int t = threadIdx.x;
    int c0 = blockIdx.x * 128, r0 = blockIdx.y * 128;
    const uint32_t* Ab = Xh + (size_t)r0 * KU;
    const uint32_t* Bb = Wh + (size_t)c0 * KU;
    int lane = t & 31, g = lane >> 2, tg = lane & 3;
    int wid = t >> 5, wy = wid & 1, wx = wid >> 1;

    float acc[4][4][4];
    #pragma unroll
    for (int i = 0; i < 4; i++)
        #pragma unroll
        for (int j = 0; j < 4; j++)
            #pragma unroll
            for (int k = 0; k < 4; k++) acc[i][j][k] = 0.0f;

    issue2(sb, 0, Ab, KU, Bb, KU, 0, t);
    for (int c = 0; c < 16; c++) {
        if (c + 1 < 16) { issue2(sb, (c + 1) & 1, Ab, KU, Bb, KU, (c + 1) * 16, t); cpwait1(); }
        else cpwait0();
        __syncthreads();
        compute_chunk(&sm[c & 1][0][0], &sm[c & 1][1][0], acc, g, tg, wy, wx);
        __syncthreads();
    }

    #pragma unroll
    for (int i = 0; i < 4; i++) {
        int R0 = r0 + wy * 64 + i * 16 + g;
        #pragma unroll
        for (int j = 0; j < 4; j++) {
            int C = c0 + wx * 32 + j * 8 + 2 * tg;
            float2 bz = *(const float2*)&bias[C];
            float2 v0 = {acc[i][j][0] + bz.x, acc[i][j][1] + bz.y};
            *(float2*)&outS[(size_t)R0 * DDIM + C] = v0;
            float2 v1 = {acc[i][j][2] + bz.x, acc[i][j][3] + bz.y};
            *(float2*)&outS[(size_t)(R0 + 8) * DDIM + C] = v1;
        }
    }
}

// ---------------- info GEMM (transposed by construction): outT[b][n][j] = w[j] * (W[n].X[b][j]) ----------------
__global__ void __launch_bounds__(256)
gemm_infoT(const uint32_t* __restrict__ Wa, const uint32_t* __restrict__ Wb,
           const uint32_t* __restrict__ Xh, int L,
           const float* __restrict__ wscale,
           uint32_t* __restrict__ out1, uint32_t* __restrict__ out2) {
    __shared__ uint32_t sm[2][2][2560];
    uint32_t sb = smem_u32(&sm[0][0][0]);
    int t = threadIdx.x;
    int widx = blockIdx.x & 1;
    int j0 = (blockIdx.x >> 1) * 128;
    int n0 = blockIdx.y * 128;
    int z = blockIdx.z;
    int Lu = L >> 1;

    const uint32_t* Ab = (widx ? Wb : Wa) + (size_t)n0 * KU;
    const uint32_t* Bb = Xh + ((size_t)z * L + j0) * KU;
    const float* ws = wscale + (size_t)z * L;
    uint32_t* ot = (widx ? out2 : out1) + (size_t)z * DDIM * Lu;

    int lane = t & 31, g = lane >> 2, tg = lane & 3;
    int wid = t >> 5, wy = wid & 1, wx = wid >> 1;

    float acc[4][4][4];
    #pragma unroll
    for (int i = 0; i < 4; i++)
        #pragma unroll
        for (int j = 0; j < 4; j++)
            #pragma unroll
            for (int k = 0; k < 4; k++) acc[i][j][k] = 0.0f;

    issue2(sb, 0, Ab, KU, Bb, KU, 0, t);
    for (int c = 0; c < 16; c++) {
        if (c + 1 < 16) { issue2(sb, (c + 1) & 1, Ab, KU, Bb, KU, (c + 1) * 16, t); cpwait1(); }
        else cpwait0();
        __syncthreads();
        compute_chunk(&sm[c & 1][0][0], &sm[c & 1][1][0], acc, g, tg, wy, wx);
        __syncthreads();
    }

    // epilogue: pack (j, j+1) half pairs, coalesced by quad (16B) x 8 rows
    #pragma unroll
    for (int i = 0; i < 4; i++) {
        int R0 = n0 + wy * 64 + i * 16 + g;
        int R1 = R0 + 8;
        #pragma unroll
        for (int j = 0; j < 4; j++) {
            int C = j0 + wx * 32 + j * 8 + 2 * tg;
            float2 s = *(const float2*)&ws[C];
            ot[(size_t)R0 * Lu + (C >> 1)] = pk(acc[i][j][0] * s.x, acc[i][j][1] * s.y);
            ot[(size_t)R1 * Lu + (C >> 1)] = pk(acc[i][j][2] * s.x, acc[i][j][3] * s.y);
        }
    }
}

// ---------------- message GEMM: out = relu(self + invnb * (A1@B1^T + A2@B2^T)) ----------------
__global__ void __launch_bounds__(256)
gemm_msg(const uint32_t* __restrict__ A1, int K1u, const uint32_t* __restrict__ B1,
         const uint32_t* __restrict__ A2, int K2u, const uint32_t* __restrict__ B2,
         const float* __restrict__ selfb, const float* __restrict__ invnb,
         float* __restrict__ out, uint32_t* __restrict__ outH, int M) {
    int z = blockIdx.z;
    A1 += (size_t)z * M * K1u;
    B1 += (size_t)z * DDIM * K1u;
    A2 += (size_t)z * M * K2u;
    B2 += (size_t)z * DDIM * K2u;
    selfb += (size_t)z * M * DDIM;
    invnb += (size_t)z * M;
    out += (size_t)z * M * DDIM;
    if (outH) outH += (size_t)z * M * KU;

    __shared__ uint32_t sm[2][2][2560];
    uint32_t sb = smem_u32(&sm[0][0][0]);
    int t = threadIdx.x;
    int c0 = blockIdx.x * 128, r0 = blockIdx.y * 128;
    const uint32_t* Ab1 = A1 + (size_t)r0 * K1u;
    const uint32_t* Bb1 = B1 + (size_t)c0 * K1u;
    const uint32_t* Ab2 = A2 + (size_t)r0 * K2u;
    const uint32_t* Bb2 = B2 + (size_t)c0 * K2u;

    int lane = t & 31, g = lane >> 2, tg = lane & 3;
    int wid = t >> 5, wy = wid & 1, wx = wid >> 1;

    float acc[4][4][4];
    #pragma unroll
    for (int i = 0; i < 4; i++)
        #pragma unroll
        for (int j = 0; j < 4; j++)
            #pragma unroll
            for (int k = 0; k < 4; k++) acc[i][j][k] = 0.0f;

    int nch = (K1u + K2u) >> 4;
    issue2(sb, 0, Ab1, K1u, Bb1, K1u, 0, t);
    for (int c = 0; c < nch; c++) {
        if (c + 1 < nch) {
            int kkU = (c + 1) * 16;
            if (kkU < K1u) issue2(sb, (c + 1) & 1, Ab1, K1u, Bb1, K1u, kkU, t);
            else           issue2(sb, (c + 1) & 1, Ab2, K2u, Bb2, K2u, kkU - K1u, t);
            cpwait1();
        } else cpwait0();
        __syncthreads();
        compute_chunk(&sm[c & 1][0][0], &sm[c & 1][1][0], acc, g, tg, wy, wx);
        __syncthreads();
    }

    #pragma unroll
    for (int i = 0; i < 4; i++) {
        int R0 = r0 + wy * 64 + i * 16 + g;
        int R1 = R0 + 8;
        float inv0 = invnb[R0], inv1 = invnb[R1];
        #pragma unroll
        for (int j = 0; j < 4; j++) {
            int C = c0 + wx * 32 + j * 8 + 2 * tg;
            float2 s0 = *(const float2*)&selfb[(size_t)R0 * DDIM + C];
            float2 v0;
            v0.x = fmaxf(s0.x + acc[i][j][0] * inv0, 0.0f);
            v0.y = fmaxf(s0.y + acc[i][j][1] * inv0, 0.0f);
            *(float2*)&out[(size_t)R0 * DDIM + C] = v0;
            float2 s1 = *(const float2*)&selfb[(size_t)R1 * DDIM + C];
            float2 v1;
            v1.x = fmaxf(s1.x + acc[i][j][2] * inv1, 0.0f);
            v1.y = fmaxf(s1.y + acc[i][j][3] * inv1, 0.0f);
            *(float2*)&out[(size_t)R1 * DDIM + C] = v1;
            if (outH) {  // fused fp16 state write for next step
                outH[(size_t)R0 * KU + (C >> 1)] = pk(v0.x, v0.y);
                outH[(size_t)R1 * KU + (C >> 1)] = pk(v1.x, v1.y);
            }
        }
    }
}

// ---------------- host orchestration ----------------
extern "C" void kernel_launch(void* const* d_in, const int* in_sizes, int n_in,
                              void* d_out_, int out_size) {
    const float* d_node = (const float*)d_in[0];
    const float* q_node = (const float*)d_in[1];
    const int*   qq     = (const int*)d_in[2];
    const int*   dq     = (const int*)d_in[3];
    const int*   dd     = (const int*)d_in[4];
    const int*   qd     = (const int*)d_in[5];
    const float* W_nw   = (const float*)d_in[6];
    const float* b_nw   = (const float*)d_in[7];
    const float* W_self = (const float*)d_in[8];
    const float* b_self = (const float*)d_in[9];
    const float* W_dd   = (const float*)d_in[10];
    const float* W_qq   = (const float*)d_in[11];
    const float* W_dq   = (const float*)d_in[12];
    const float* W_qd   = (const float*)d_in[13];

    float* out = (float*)d_out_;
    float* out_dnode = out;
    float* out_qnode = out + (size_t)BB * LDN * DDIM;
    float* out_dw    = out_qnode + (size_t)BB * LQN * DDIM;
    float* out_qw    = out_dw + (size_t)BB * 2 * LDN;

    float *p_self_d, *p_self_q, *p_dcur, *p_qcur, *p_dnb, *p_qnb, *p_dw, *p_qw;
    uint32_t *p_xdh, *p_xqh, *p_ddh, *p_dqh, *p_qqh, *p_qdh;
    uint32_t *p_sddh, *p_sqdh, *p_sqqh, *p_sdqh, *p_wh;
    cudaGetSymbolAddress((void**)&p_self_d, g_self_d);
    cudaGetSymbolAddress((void**)&p_self_q, g_self_q);
    cudaGetSymbolAddress((void**)&p_dcur, g_dcur);
    cudaGetSymbolAddress((void**)&p_qcur, g_qcur);
    cudaGetSymbolAddress((void**)&p_dnb, g_dnb);
    cudaGetSymbolAddress((void**)&p_qnb, g_qnb);
    cudaGetSymbolAddress((void**)&p_dw, g_dw);
    cudaGetSymbolAddress((void**)&p_qw, g_qw);
    cudaGetSymbolAddress((void**)&p_xdh, g_xdh);
    cudaGetSymbolAddress((void**)&p_xqh, g_xqh);
    cudaGetSymbolAddress((void**)&p_ddh, g_ddh);
    cudaGetSymbolAddress((void**)&p_dqh, g_dqh);
    cudaGetSymbolAddress((void**)&p_qqh, g_qqh);
    cudaGetSymbolAddress((void**)&p_qdh, g_qdh);
    cudaGetSymbolAddress((void**)&p_sddh, g_sddh);
    cudaGetSymbolAddress((void**)&p_sqdh, g_sqdh);
    cudaGetSymbolAddress((void**)&p_sqqh, g_sqqh);
    cudaGetSymbolAddress((void**)&p_sdqh, g_sdqh);
    cudaGetSymbolAddress((void**)&p_wh, g_wh);

    const uint32_t* wh_self = p_wh;
    const uint32_t* wh_dd   = p_wh + 1 * (size_t)DDIM * KU;
    const uint32_t* wh_qd   = p_wh + 2 * (size_t)DDIM * KU;
    const uint32_t* wh_qq   = p_wh + 3 * (size_t)DDIM * KU;
    const uint32_t* wh_dq   = p_wh + 4 * (size_t)DDIM * KU;

    // one-time conversions
    cvt_w<<<320, 256>>>(W_self, W_dd, W_qd, W_qq, W_dq, p_wh);
    cvt_i2h<<<1184, 256>>>(dd, p_ddh, BB * LDN * LDN / 4);
    cvt_i2h<<<592, 256>>>(dq, p_dqh, BB * LDN * LQN / 4);
    cvt_i2h<<<592, 256>>>(qd, p_qdh, BB * LQN * LDN / 4);
    cvt_i2h<<<296, 256>>>(qq, p_qqh, BB * LQN * LQN / 4);
    nb_kernel<<<BB * LDN / 8, 256>>>(dd, dq, LDN, LQN, BB * LDN, p_dnb);
    nb_kernel<<<BB * LQN / 8, 256>>>(qq, qd, LQN, LDN, BB * LQN, p_qnb);
    // step-0 node features to fp16
    cvt_f2h<<<1184, 256>>>(d_node, p_xdh, BB * LDN * DDIM / 4);
    cvt_f2h<<<592, 256>>>(q_node, p_xqh, BB * LQN * DDIM / 4);

    const float* Xd = d_node;
    const float* Xq = q_node;

    for (int t = 0; t < 2; t++) {
        bool last = (t == 1);

        nw_kernel<<<BB * LDN / 8, 256>>>(Xd, W_nw, b_nw, p_dw, out_dw + t * LDN,
                                         BB * LDN, LDN, 2 * LDN);
        nw_kernel<<<BB * LQN / 8, 256>>>(Xq, W_nw, b_nw, p_qw, out_qw + t * LQN,
                                         BB * LQN, LQN, 2 * LQN);

        gemm_self<<<dim3(4, BB * LDN / 128), 256>>>(p_xdh, wh_self, b_self, p_self_d);
        gemm_self<<<dim3(4, BB * LQN / 128), 256>>>(p_xqh, wh_self, b_self, p_self_q);

        gemm_infoT<<<dim3(8, 4, BB), 256>>>(wh_dd, wh_qd, p_xdh, LDN, p_dw, p_sddh, p_sqdh);
        gemm_infoT<<<dim3(2, 4, BB), 256>>>(wh_qq, wh_dq, p_xqh, LQN, p_qw, p_sqqh, p_sdqh);

        float* outd = last ? out_dnode : p_dcur;
        float* outq = last ? out_qnode : p_qcur;
        gemm_msg<<<dim3(4, LDN / 128, BB), 256>>>(
            p_ddh, LDN / 2, p_sddh, p_dqh, LQN / 2, p_sdqh,
            p_self_d, p_dnb, outd, last ? nullptr : p_xdh, LDN);
        gemm_msg<<<dim3(4, LQN / 128, BB), 256>>>(
            p_qqh, LQN / 2, p_sqqh, p_qdh, LDN / 2, p_sqdh,
            p_self_q, p_qnb, outq, last ? nullptr : p_xqh, LQN);
        Xd = outd;
        Xq = outq;
    }
    (void)in_sizes; (void)n_in; (void)out_size;
}

// round 6
// speedup vs baseline: 4.9099x; 1.0886x over previous
#include <cuda_runtime.h>
#include <cuda_fp16.h>
#include <math.h>
#include <stdint.h>

#define BB 64
#define LDN 512
#define LQN 128
#define DDIM 512
#define KU   (DDIM/2)   // 256 uints (half2) per feature row
#define KG   320        // graph-part row width in uints: (512+128)/2
#define RSH  20         // smem row stride in uints: 16 data + 4 pad (conflict-free frags)

// ---------------- fp16 buffers (uint32 = half2, pairs along K) ----------------
__device__ uint32_t g_xdh[(size_t)BB*LDN*KU];    // d state (step input)
__device__ uint32_t g_xqh[(size_t)BB*LQN*KU];
__device__ uint32_t g_xdh2[(size_t)BB*LDN*KU];   // d state (next step)
__device__ uint32_t g_xqh2[(size_t)BB*LQN*KU];
__device__ uint32_t g_adh[(size_t)BB*LDN*KG];    // inv⊙[dd | dq] per d-row
__device__ uint32_t g_aqh[(size_t)BB*LQN*KG];    // inv⊙[qq | qd] per q-row
__device__ uint32_t g_bdh[(size_t)BB*DDIM*KG];   // [dd_info(256u) | dq_info(64u)] per n
__device__ uint32_t g_bqh[(size_t)BB*DDIM*KG];   // [qq_info(64u)  | qd_info(256u)] per n
__device__ uint32_t g_wh[5][(size_t)DDIM*KU];    // self, dd, qd, qq, dq
__device__ float g_dw[BB*LDN];
__device__ float g_qw[BB*LQN];

// ---------------- helpers ----------------
__device__ __forceinline__ uint32_t pk(float lo, float hi) {
    uint32_t u;
    asm("cvt.rn.f16x2.f32 %0, %1, %2;" : "=r"(u) : "f"(hi), "f"(lo));
    return u;
}
__device__ __forceinline__ void mma16(float* c, const uint32_t* a, const uint32_t* b) {
    asm volatile(
        "mma.sync.aligned.m16n8k16.row.col.f32.f16.f16.f32 "
        "{%0,%1,%2,%3}, {%4,%5,%6,%7}, {%8,%9}, {%0,%1,%2,%3};"
        : "+f"(c[0]), "+f"(c[1]), "+f"(c[2]), "+f"(c[3])
        : "r"(a[0]), "r"(a[1]), "r"(a[2]), "r"(a[3]), "r"(b[0]), "r"(b[1]));
}
__device__ __forceinline__ uint32_t smem_u32(const void* p) {
    uint32_t a;
    asm("{ .reg .u64 t; cvta.to.shared.u64 t, %1; cvt.u32.u64 %0, t; }" : "=r"(a) : "l"(p));
    return a;
}
__device__ __forceinline__ void cp16(uint32_t daddr, const uint32_t* g) {
    asm volatile("cp.async.cg.shared.global [%0], [%1], 16;"
                 :: "r"(daddr), "l"(__cvta_generic_to_global((void*)g)));
}
__device__ __forceinline__ void cpcommit() { asm volatile("cp.async.commit_group;"); }
__device__ __forceinline__ void cpwait0()  { asm volatile("cp.async.wait_group 0;"); }
__device__ __forceinline__ void cpwait1()  { asm volatile("cp.async.wait_group 1;"); }

// stage one 128x32half tile pair (A,B) into buf via cp.async; 2x16B per thread per operand
__device__ __forceinline__ void issue2(uint32_t sb, int buf,
                                       const uint32_t* Asrc, int sA,
                                       const uint32_t* Bsrc, int sB,
                                       int kkU, int t) {
    #pragma unroll
    for (int s = 0; s < 2; s++) {
        int idx = t * 2 + s, row = idx >> 2, c4 = idx & 3;
        uint32_t off = (uint32_t)((row * RSH + c4 * 4) * 4);
        cp16(sb + (uint32_t)(buf * 2 + 0) * 10240u + off, Asrc + (size_t)row * sA + kkU + c4 * 4);
        cp16(sb + (uint32_t)(buf * 2 + 1) * 10240u + off, Bsrc + (size_t)row * sB + kkU + c4 * 4);
    }
    cpcommit();
}

__device__ __forceinline__ void compute_chunk(const uint32_t* As, const uint32_t* Bs,
                                              float acc[4][4][4],
                                              int g, int tg, int wy, int wx) {
    #pragma unroll
    for (int k16 = 0; k16 < 2; k16++) {
        int kb = k16 * 8;
        uint32_t a[4][4], b[4][2];
        #pragma unroll
        for (int i = 0; i < 4; i++) {
            int R = wy * 64 + i * 16 + g;
            a[i][0] = As[R * RSH + kb + tg];
            a[i][1] = As[(R + 8) * RSH + kb + tg];
            a[i][2] = As[R * RSH + kb + tg + 4];
            a[i][3] = As[(R + 8) * RSH + kb + tg + 4];
        }
        #pragma unroll
        for (int j = 0; j < 4; j++) {
            int C = wx * 32 + j * 8 + g;
            b[j][0] = Bs[C * RSH + kb + tg];
            b[j][1] = Bs[C * RSH + kb + tg + 4];
        }
        #pragma unroll
        for (int i = 0; i < 4; i++)
            #pragma unroll
            for (int j = 0; j < 4; j++)
                mma16(acc[i][j], a[i], b[j]);
    }
}

// ---------------- conversion kernels ----------------
__global__ void cvt_f2h(const float* __restrict__ s, uint32_t* __restrict__ d, int n4) {
    int i = blockIdx.x * blockDim.x + threadIdx.x;
    int st = gridDim.x * blockDim.x;
    for (; i < n4; i += st) {
        float4 v = *(const float4*)(s + (size_t)i * 4);
        uint2 o = {pk(v.x, v.y), pk(v.z, v.w)};
        *(uint2*)(d + (size_t)i * 2) = o;
    }
}
__global__ void cvt_w(const float* __restrict__ w0, const float* __restrict__ w1,
                      const float* __restrict__ w2, const float* __restrict__ w3,
                      const float* __restrict__ w4, uint32_t* __restrict__ dst) {
    int i = blockIdx.x * blockDim.x + threadIdx.x;
    int st = gridDim.x * blockDim.x;
    for (; i < 5 * 65536; i += st) {
        int which = i >> 16, off = i & 65535;
        const float* w = which == 0 ? w0 : which == 1 ? w1 : which == 2 ? w2
                       : which == 3 ? w3 : w4;
        float4 v = *(const float4*)(w + (size_t)off * 4);
        uint2 o = {pk(v.x, v.y), pk(v.z, v.w)};
        *(uint2*)(dst + (size_t)i * 2) = o;
    }
}

// ---------------- fused neighbor count + inv-scaled fp16 graph conversion ----------------
// outA[w][0..K1/2) = inv*A1 pairs, [K1/2..(K1+K2)/2) = inv*A2 pairs
__global__ void nbcvt(const int* __restrict__ A1, const int* __restrict__ A2,
                      int K1, int K2, int nrows, uint32_t* __restrict__ outA) {
    int w = (blockIdx.x * blockDim.x + threadIdx.x) >> 5;
    int lane = threadIdx.x & 31;
    if (w >= nrows) return;
    const int2* r1 = (const int2*)(A1 + (size_t)w * K1);
    const int2* r2 = (const int2*)(A2 + (size_t)w * K2);
    int Ku1 = K1 >> 1, Kt = (K1 + K2) >> 1;
    int s = 0;
    for (int u = lane; u < Ku1; u += 32) { int2 v = r1[u]; s += v.x + v.y; }
    for (int u = lane; u < Kt - Ku1; u += 32) { int2 v = r2[u]; s += v.x + v.y; }
    #pragma unroll
    for (int o = 16; o; o >>= 1) s += __shfl_xor_sync(0xFFFFFFFFu, s, o);
    float inv = 1.0f / ((s < 1) ? 1.0f : (float)s);
    uint32_t* orow = outA + (size_t)w * Kt;
    for (int u = lane; u < Kt; u += 32) {
        int2 v = (u < Ku1) ? r1[u] : r2[u - Ku1];
        orow[u] = pk(inv * (float)v.x, inv * (float)v.y);
    }
}

// ---------------- node weights from fp16 state: sigmoid(x . W_nw + b_nw) ----------------
__global__ void nw_h(const uint32_t* __restrict__ Xh, const float* __restrict__ Wnw,
                     const float* __restrict__ bnw,
                     float* __restrict__ wbuf, float* __restrict__ outw,
                     int nrows, int L, int stride_b) {
    int w = (blockIdx.x * blockDim.x + threadIdx.x) >> 5;
    int lane = threadIdx.x & 31;
    if (w >= nrows) return;
    const uint32_t* x = Xh + (size_t)w * KU;
    float s = 0.0f;
    #pragma unroll 4
    for (int u = lane; u < KU; u += 32) {
        float2 h = __half22float2(*(const __half2*)&x[u]);
        s += h.x * Wnw[2 * u] + h.y * Wnw[2 * u + 1];
    }
    #pragma unroll
    for (int o = 16; o; o >>= 1) s += __shfl_xor_sync(0xFFFFFFFFu, s, o);
    if (lane == 0) {
        float z = s + bnw[0];
        float v = 1.0f / (1.0f + expf(-z));
        wbuf[w] = v;
        int b = w / L, l = w - b * L;
        outw[(size_t)b * stride_b + l] = v;
    }
}

// ---------------- info GEMM (transposed by construction) ----------------
// out[z][n][off + j/2] = pack of w[j]*(W[n].X[z][j]); out row stride KG
__global__ void __launch_bounds__(256)
gemm_infoT(const uint32_t* __restrict__ Wa, const uint32_t* __restrict__ Wb,
           const uint32_t* __restrict__ Xh, int L,
           const float* __restrict__ wscale,
           uint32_t* __restrict__ out1, int off1,
           uint32_t* __restrict__ out2, int off2) {
    __shared__ uint32_t sm[2][2][2560];
    uint32_t sb = smem_u32(&sm[0][0][0]);
    int t = threadIdx.x;
    int widx = blockIdx.x & 1;
    int j0 = (blockIdx.x >> 1) * 128;
    int n0 = blockIdx.y * 128;
    int z = blockIdx.z;

    const uint32_t* Ab = (widx ? Wb : Wa) + (size_t)n0 * KU;
    const uint32_t* Bb = Xh + ((size_t)z * L + j0) * KU;
    const float* ws = wscale + (size_t)z * L;
    uint32_t* ot = (widx ? out2 : out1) + (size_t)z * DDIM * KG + (widx ? off2 : off1);

    int lane = t & 31, g = lane >> 2, tg = lane & 3;
    int wid = t >> 5, wy = wid & 1, wx = wid >> 1;

    float acc[4][4][4];
    #pragma unroll
    for (int i = 0; i < 4; i++)
        #pragma unroll
        for (int j = 0; j < 4; j++)
            #pragma unroll
            for (int k = 0; k < 4; k++) acc[i][j][k] = 0.0f;

    issue2(sb, 0, Ab, KU, Bb, KU, 0, t);
    for (int c = 0; c < 16; c++) {
        if (c + 1 < 16) { issue2(sb, (c + 1) & 1, Ab, KU, Bb, KU, (c + 1) * 16, t); cpwait1(); }
        else cpwait0();
        __syncthreads();
        compute_chunk(&sm[c & 1][0][0], &sm[c & 1][1][0], acc, g, tg, wy, wx);
        __syncthreads();
    }

    #pragma unroll
    for (int i = 0; i < 4; i++) {
        int R0 = n0 + wy * 64 + i * 16 + g;
        int R1 = R0 + 8;
        #pragma unroll
        for (int j = 0; j < 4; j++) {
            int C = j0 + wx * 32 + j * 8 + 2 * tg;
            float2 s = *(const float2*)&ws[C];
            ot[(size_t)R0 * KG + (C >> 1)] = pk(acc[i][j][0] * s.x, acc[i][j][1] * s.y);
            ot[(size_t)R1 * KG + (C >> 1)] = pk(acc[i][j][2] * s.x, acc[i][j][3] * s.y);
        }
    }
}

// ---------------- unified message+self GEMM ----------------
// out[z][i][n] = relu( ([inv⊙A | X] @ [Binfo ; Wself])[i][n] + bias[n] )
// A-part: Ag rows stride KG (20 chunks); X-part: Xh rows stride KU (16 chunks).
__global__ void __launch_bounds__(256)
gemm_msg(const uint32_t* __restrict__ Ag, const uint32_t* __restrict__ Xh,
         const uint32_t* __restrict__ Bg, const uint32_t* __restrict__ Wse,
         const float* __restrict__ bias,
         float* __restrict__ out, uint32_t* __restrict__ outH, int M) {
    int z = blockIdx.z;
    Ag += (size_t)z * M * KG;
    Xh += (size_t)z * M * KU;
    Bg += (size_t)z * DDIM * KG;
    if (out)  out  += (size_t)z * M * DDIM;
    if (outH) outH += (size_t)z * M * KU;

    __shared__ uint32_t sm[2][2][2560];
    uint32_t sb = smem_u32(&sm[0][0][0]);
    int t = threadIdx.x;
    int c0 = blockIdx.x * 128, r0 = blockIdx.y * 128;
    const uint32_t* Ab1 = Ag + (size_t)r0 * KG;
    const uint32_t* Ab2 = Xh + (size_t)r0 * KU;
    const uint32_t* Bb1 = Bg + (size_t)c0 * KG;
    const uint32_t* Bb2 = Wse + (size_t)c0 * KU;

    int lane = t & 31, g = lane >> 2, tg = lane & 3;
    int wid = t >> 5, wy = wid & 1, wx = wid >> 1;

    float acc[4][4][4];
    #pragma unroll
    for (int i = 0; i < 4; i++)
        #pragma unroll
        for (int j = 0; j < 4; j++)
            #pragma unroll
            for (int k = 0; k < 4; k++) acc[i][j][k] = 0.0f;

    const int nch = 36;  // 20 graph chunks + 16 feature chunks
    issue2(sb, 0, Ab1, KG, Bb1, KG, 0, t);
    for (int c = 0; c < nch; c++) {
        if (c + 1 < nch) {
            int kkU = (c + 1) * 16;
            if (kkU < KG) issue2(sb, (c + 1) & 1, Ab1, KG, Bb1, KG, kkU, t);
            else          issue2(sb, (c + 1) & 1, Ab2, KU, Bb2, KU, kkU - KG, t);
            cpwait1();
        } else cpwait0();
        __syncthreads();
        compute_chunk(&sm[c & 1][0][0], &sm[c & 1][1][0], acc, g, tg, wy, wx);
        __syncthreads();
    }

    #pragma unroll
    for (int i = 0; i < 4; i++) {
        int R0 = r0 + wy * 64 + i * 16 + g;
        int R1 = R0 + 8;
        #pragma unroll
        for (int j = 0; j < 4; j++) {
            int C = c0 + wx * 32 + j * 8 + 2 * tg;
            float2 bz = *(const float2*)&bias[C];
            float2 v0, v1;
            v0.x = fmaxf(acc[i][j][0] + bz.x, 0.0f);
            v0.y = fmaxf(acc[i][j][1] + bz.y, 0.0f);
            v1.x = fmaxf(acc[i][j][2] + bz.x, 0.0f);
            v1.y = fmaxf(acc[i][j][3] + bz.y, 0.0f);
            if (out) {
                *(float2*)&out[(size_t)R0 * DDIM + C] = v0;
                *(float2*)&out[(size_t)R1 * DDIM + C] = v1;
            }
            if (outH) {
                outH[(size_t)R0 * KU + (C >> 1)] = pk(v0.x, v0.y);
                outH[(size_t)R1 * KU + (C >> 1)] = pk(v1.x, v1.y);
            }
        }
    }
}

// ---------------- host orchestration ----------------
extern "C" void kernel_launch(void* const* d_in, const int* in_sizes, int n_in,
                              void* d_out_, int out_size) {
    const float* d_node = (const float*)d_in[0];
    const float* q_node = (const float*)d_in[1];
    const int*   qq     = (const int*)d_in[2];
    const int*   dq     = (const int*)d_in[3];
    const int*   dd     = (const int*)d_in[4];
    const int*   qd     = (const int*)d_in[5];
    const float* W_nw   = (const float*)d_in[6];
    const float* b_nw   = (const float*)d_in[7];
    const float* W_self = (const float*)d_in[8];
    const float* b_self = (const float*)d_in[9];
    const float* W_dd   = (const float*)d_in[10];
    const float* W_qq   = (const float*)d_in[11];
    const float* W_dq   = (const float*)d_in[12];
    const float* W_qd   = (const float*)d_in[13];

    float* out = (float*)d_out_;
    float* out_dnode = out;
    float* out_qnode = out + (size_t)BB * LDN * DDIM;
    float* out_dw    = out_qnode + (size_t)BB * LQN * DDIM;
    float* out_qw    = out_dw + (size_t)BB * 2 * LDN;

    float *p_dw, *p_qw;
    uint32_t *p_xdh, *p_xqh, *p_xdh2, *p_xqh2, *p_adh, *p_aqh, *p_bdh, *p_bqh, *p_wh;
    cudaGetSymbolAddress((void**)&p_dw, g_dw);
    cudaGetSymbolAddress((void**)&p_qw, g_qw);
    cudaGetSymbolAddress((void**)&p_xdh, g_xdh);
    cudaGetSymbolAddress((void**)&p_xqh, g_xqh);
    cudaGetSymbolAddress((void**)&p_xdh2, g_xdh2);
    cudaGetSymbolAddress((void**)&p_xqh2, g_xqh2);
    cudaGetSymbolAddress((void**)&p_adh, g_adh);
    cudaGetSymbolAddress((void**)&p_aqh, g_aqh);
    cudaGetSymbolAddress((void**)&p_bdh, g_bdh);
    cudaGetSymbolAddress((void**)&p_bqh, g_bqh);
    cudaGetSymbolAddress((void**)&p_wh, g_wh);

    const uint32_t* wh_self = p_wh;
    const uint32_t* wh_dd   = p_wh + 1 * (size_t)DDIM * KU;
    const uint32_t* wh_qd   = p_wh + 2 * (size_t)DDIM * KU;
    const uint32_t* wh_qq   = p_wh + 3 * (size_t)DDIM * KU;
    const uint32_t* wh_dq   = p_wh + 4 * (size_t)DDIM * KU;

    // one-time conversions
    cvt_w<<<320, 256>>>(W_self, W_dd, W_qd, W_qq, W_dq, p_wh);
    nbcvt<<<BB * LDN / 8, 256>>>(dd, dq, LDN, LQN, BB * LDN, p_adh);
    nbcvt<<<BB * LQN / 8, 256>>>(qq, qd, LQN, LDN, BB * LQN, p_aqh);
    cvt_f2h<<<1184, 256>>>(d_node, p_xdh, BB * LDN * DDIM / 4);
    cvt_f2h<<<592, 256>>>(q_node, p_xqh, BB * LQN * DDIM / 4);

    uint32_t* xd = p_xdh;
    uint32_t* xq = p_xqh;
    uint32_t* xd_next = p_xdh2;
    uint32_t* xq_next = p_xqh2;

    for (int t = 0; t < 2; t++) {
        bool last = (t == 1);

        nw_h<<<BB * LDN / 8, 256>>>(xd, W_nw, b_nw, p_dw, out_dw + t * LDN,
                                    BB * LDN, LDN, 2 * LDN);
        nw_h<<<BB * LQN / 8, 256>>>(xq, W_nw, b_nw, p_qw, out_qw + t * LQN,
                                    BB * LQN, LQN, 2 * LQN);

        // info GEMMs: d-feeds (dd_info -> bdh[0..], qd_info -> bqh[64..])
        //             q-feeds (qq_info -> bqh[0..], dq_info -> bdh[256..])
        gemm_infoT<<<dim3(8, 4, BB), 256>>>(wh_dd, wh_qd, xd, LDN, p_dw,
                                            p_bdh, 0, p_bqh, 64);
        gemm_infoT<<<dim3(2, 4, BB), 256>>>(wh_qq, wh_dq, xq, LQN, p_qw,
                                            p_bqh, 0, p_bdh, 256);

        // unified message+self GEMMs
        gemm_msg<<<dim3(4, LDN / 128, BB), 256>>>(
            p_adh, xd, p_bdh, wh_self, b_self,
            last ? out_dnode : nullptr, last ? nullptr : xd_next, LDN);
        gemm_msg<<<dim3(4, LQN / 128, BB), 256>>>(
            p_aqh, xq, p_bqh, wh_self, b_self,
            last ? out_qnode : nullptr, last ? nullptr : xq_next, LQN);

        uint32_t* tmp;
        tmp = xd; xd = xd_next; xd_next = tmp;
        tmp = xq; xq = xq_next; xq_next = tmp;
    }
    (void)in_sizes; (void)n_in; (void)out_size;
}

// round 7
// speedup vs baseline: 5.1608x; 1.0511x over previous
#include <cuda_runtime.h>
#include <cuda_fp16.h>
#include <math.h>
#include <stdint.h>

#define BB 64
#define LDN 512
#define LQN 128
#define DDIM 512
#define KU   (DDIM/2)   // 256 uints (half2) per feature row
#define KG   320        // graph-part row width in uints: (512+128)/2
#define RSH  20         // smem row stride in uints: 16 data + 4 pad (conflict-free)
#define STAGE_B 20480u  // bytes per pipeline stage (A 10240 + B 10240)
#define SMEM_DYN (3 * 20480)

// ---------------- fp16 buffers (uint32 = half2, pairs along K) ----------------
__device__ uint32_t g_xdh[(size_t)BB*LDN*KU];    // d state (step input)
__device__ uint32_t g_xqh[(size_t)BB*LQN*KU];
__device__ uint32_t g_xdh2[(size_t)BB*LDN*KU];   // d state (next step)
__device__ uint32_t g_xqh2[(size_t)BB*LQN*KU];
__device__ uint32_t g_adh[(size_t)BB*LDN*KG];    // inv⊙[dd | dq] per d-row
__device__ uint32_t g_aqh[(size_t)BB*LQN*KG];    // inv⊙[qq | qd] per q-row
__device__ uint32_t g_bdh[(size_t)BB*DDIM*KG];   // [dd_info(256u) | dq_info(64u)] per n
__device__ uint32_t g_bqh[(size_t)BB*DDIM*KG];   // [qq_info(64u)  | qd_info(256u)] per n
__device__ uint32_t g_wh[5][(size_t)DDIM*KU];    // self, dd, qd, qq, dq
__device__ float g_dw[BB*LDN];
__device__ float g_qw[BB*LQN];

// ---------------- helpers ----------------
__device__ __forceinline__ uint32_t pk(float lo, float hi) {
    uint32_t u;
    asm("cvt.rn.f16x2.f32 %0, %1, %2;" : "=r"(u) : "f"(hi), "f"(lo));
    return u;
}
__device__ __forceinline__ void mma16(float* c, const uint32_t* a, const uint32_t* b) {
    asm volatile(
        "mma.sync.aligned.m16n8k16.row.col.f32.f16.f16.f32 "
        "{%0,%1,%2,%3}, {%4,%5,%6,%7}, {%8,%9}, {%0,%1,%2,%3};"
        : "+f"(c[0]), "+f"(c[1]), "+f"(c[2]), "+f"(c[3])
        : "r"(a[0]), "r"(a[1]), "r"(a[2]), "r"(a[3]), "r"(b[0]), "r"(b[1]));
}
__device__ __forceinline__ void ldm4(uint32_t* r, uint32_t addr) {
    asm volatile("ldmatrix.sync.aligned.m8n8.x4.shared.b16 {%0,%1,%2,%3}, [%4];"
                 : "=r"(r[0]), "=r"(r[1]), "=r"(r[2]), "=r"(r[3]) : "r"(addr));
}
__device__ __forceinline__ uint32_t smem_u32(const void* p) {
    uint32_t a;
    asm("{ .reg .u64 t; cvta.to.shared.u64 t, %1; cvt.u32.u64 %0, t; }" : "=r"(a) : "l"(p));
    return a;
}
__device__ __forceinline__ void cp16(uint32_t daddr, const uint32_t* g) {
    asm volatile("cp.async.cg.shared.global [%0], [%1], 16;"
                 :: "r"(daddr), "l"(__cvta_generic_to_global((void*)g)));
}
__device__ __forceinline__ void cpcommit() { asm volatile("cp.async.commit_group;"); }
__device__ __forceinline__ void cpwait0()  { asm volatile("cp.async.wait_group 0;"); }
__device__ __forceinline__ void cpwait1()  { asm volatile("cp.async.wait_group 1;"); }

// stage one 128x32half tile pair (A,B) into 3-stage ring buffer via cp.async
__device__ __forceinline__ void issue3(uint32_t sb, int buf,
                                       const uint32_t* Asrc, int sA,
                                       const uint32_t* Bsrc, int sB,
                                       int kkU, int t) {
    uint32_t base = sb + (uint32_t)buf * STAGE_B;
    #pragma unroll
    for (int s = 0; s < 2; s++) {
        int idx = t * 2 + s, row = idx >> 2, c4 = idx & 3;
        uint32_t off = (uint32_t)((row * RSH + c4 * 4) * 4);
        cp16(base + off,          Asrc + (size_t)row * sA + kkU + c4 * 4);
        cp16(base + 10240u + off, Bsrc + (size_t)row * sB + kkU + c4 * 4);
    }
    cpcommit();
}

// ldmatrix-based 32-K chunk compute
__device__ __forceinline__ void compute_chunk(uint32_t aBase, uint32_t bBase,
                                              uint32_t so, float acc[4][4][4]) {
    #pragma unroll
    for (int kb = 0; kb < 2; kb++) {
        uint32_t a[4][4], bb[2][4];
        #pragma unroll
        for (int i = 0; i < 4; i++)
            ldm4(a[i], aBase + so + (uint32_t)((i * 16 * RSH + kb * 8) * 4));
        #pragma unroll
        for (int p = 0; p < 2; p++)
            ldm4(bb[p], bBase + so + (uint32_t)((p * 16 * RSH + kb * 8) * 4));
        uint32_t b2[4][2] = {{bb[0][0], bb[0][2]}, {bb[0][1], bb[0][3]},
                             {bb[1][0], bb[1][2]}, {bb[1][1], bb[1][3]}};
        #pragma unroll
        for (int i = 0; i < 4; i++)
            #pragma unroll
            for (int j = 0; j < 4; j++)
                mma16(acc[i][j], a[i], b2[j]);
    }
}

// ---------------- conversion kernels ----------------
__global__ void cvt2(const float* __restrict__ dsrc, const float* __restrict__ qsrc,
                     uint32_t* __restrict__ dd, uint32_t* __restrict__ dq) {
    const int n4d = BB * LDN * DDIM / 4;
    const int n4t = n4d + BB * LQN * DDIM / 4;
    int i = blockIdx.x * blockDim.x + threadIdx.x;
    int st = gridDim.x * blockDim.x;
    for (; i < n4t; i += st) {
        const float* s;
        uint32_t* d;
        int off;
        if (i < n4d) { s = dsrc; d = dd; off = i; }
        else         { s = qsrc; d = dq; off = i - n4d; }
        float4 v = *(const float4*)(s + (size_t)off * 4);
        uint2 o = {pk(v.x, v.y), pk(v.z, v.w)};
        *(uint2*)(d + (size_t)off * 2) = o;
    }
}
__global__ void cvt_w(const float* __restrict__ w0, const float* __restrict__ w1,
                      const float* __restrict__ w2, const float* __restrict__ w3,
                      const float* __restrict__ w4, uint32_t* __restrict__ dst) {
    int i = blockIdx.x * blockDim.x + threadIdx.x;
    int st = gridDim.x * blockDim.x;
    for (; i < 5 * 65536; i += st) {
        int which = i >> 16, off = i & 65535;
        const float* w = which == 0 ? w0 : which == 1 ? w1 : which == 2 ? w2
                       : which == 3 ? w3 : w4;
        float4 v = *(const float4*)(w + (size_t)off * 4);
        uint2 o = {pk(v.x, v.y), pk(v.z, v.w)};
        *(uint2*)(dst + (size_t)i * 2) = o;
    }
}

// ---------------- fused neighbor count + inv-scaled fp16 graph conversion ----------------
__device__ __forceinline__ void nbrow(const int* A1, const int* A2, int K1, int K2,
                                      int w, int lane, uint32_t* outA) {
    const int2* r1 = (const int2*)(A1 + (size_t)w * K1);
    const int2* r2 = (const int2*)(A2 + (size_t)w * K2);
    int Ku1 = K1 >> 1, Kt = (K1 + K2) >> 1;
    int s = 0;
    for (int u = lane; u < Ku1; u += 32) { int2 v = r1[u]; s += v.x + v.y; }
    for (int u = lane; u < Kt - Ku1; u += 32) { int2 v = r2[u]; s += v.x + v.y; }
    #pragma unroll
    for (int o = 16; o; o >>= 1) s += __shfl_xor_sync(0xFFFFFFFFu, s, o);
    float inv = 1.0f / ((s < 1) ? 1.0f : (float)s);
    uint32_t* orow = outA + (size_t)w * Kt;
    for (int u = lane; u < Kt; u += 32) {
        int2 v = (u < Ku1) ? r1[u] : r2[u - Ku1];
        orow[u] = pk(inv * (float)v.x, inv * (float)v.y);
    }
}
__global__ void nbcvt2(const int* __restrict__ dd, const int* __restrict__ dq,
                       const int* __restrict__ qq, const int* __restrict__ qd,
                       uint32_t* __restrict__ outAd, uint32_t* __restrict__ outAq) {
    int w = (blockIdx.x * blockDim.x + threadIdx.x) >> 5;
    int lane = threadIdx.x & 31;
    int nd = BB * LDN;
    if (w < nd) nbrow(dd, dq, LDN, LQN, w, lane, outAd);
    else {
        w -= nd;
        if (w < BB * LQN) nbrow(qq, qd, LQN, LDN, w, lane, outAq);
    }
}

// ---------------- node weights from fp16 state: sigmoid(x . W_nw + b_nw) ----------------
__global__ void nw_h(const uint32_t* __restrict__ Xh, const float* __restrict__ Wnw,
                     const float* __restrict__ bnw,
                     float* __restrict__ wbuf, float* __restrict__ outw,
                     int nrows, int L, int stride_b) {
    int w = (blockIdx.x * blockDim.x + threadIdx.x) >> 5;
    int lane = threadIdx.x & 31;
    if (w >= nrows) return;
    const uint32_t* x = Xh + (size_t)w * KU;
    float s = 0.0f;
    #pragma unroll 4
    for (int u = lane; u < KU; u += 32) {
        float2 h = __half22float2(*(const __half2*)&x[u]);
        s += h.x * Wnw[2 * u] + h.y * Wnw[2 * u + 1];
    }
    #pragma unroll
    for (int o = 16; o; o >>= 1) s += __shfl_xor_sync(0xFFFFFFFFu, s, o);
    if (lane == 0) {
        float z = s + bnw[0];
        float v = 1.0f / (1.0f + expf(-z));
        wbuf[w] = v;
        int b = w / L, l = w - b * L;
        outw[(size_t)b * stride_b + l] = v;
    }
}

// ---------------- info GEMM (transposed by construction) ----------------
__global__ void __launch_bounds__(256)
gemm_infoT(const uint32_t* __restrict__ Wa, const uint32_t* __restrict__ Wb,
           const uint32_t* __restrict__ Xh, int L,
           const float* __restrict__ wscale,
           uint32_t* __restrict__ out1, int off1,
           uint32_t* __restrict__ out2, int off2) {
    extern __shared__ uint32_t smd[];
    uint32_t sb = smem_u32(smd);
    int t = threadIdx.x;
    int widx = blockIdx.x & 1;
    int j0 = (blockIdx.x >> 1) * 128;
    int n0 = blockIdx.y * 128;
    int z = blockIdx.z;

    const uint32_t* Ab = (widx ? Wb : Wa) + (size_t)n0 * KU;
    const uint32_t* Bb = Xh + ((size_t)z * L + j0) * KU;
    const float* ws = wscale + (size_t)z * L;
    uint32_t* ot = (widx ? out2 : out1) + (size_t)z * DDIM * KG + (widx ? off2 : off1);

    int lane = t & 31, g = lane >> 2, tg = lane & 3;
    int wid = t >> 5, wy = wid & 1, wx = wid >> 1;
    uint32_t aBase = sb + (uint32_t)(((wy * 64 + (lane & 15)) * RSH + (lane >> 4) * 4) * 4);
    uint32_t bBase = sb + 10240u +
                     (uint32_t)(((wx * 32 + (lane & 15)) * RSH + (lane >> 4) * 4) * 4);

    float acc[4][4][4];
    #pragma unroll
    for (int i = 0; i < 4; i++)
        #pragma unroll
        for (int j = 0; j < 4; j++)
            #pragma unroll
            for (int k = 0; k < 4; k++) acc[i][j][k] = 0.0f;

    issue3(sb, 0, Ab, KU, Bb, KU, 0, t);
    issue3(sb, 1, Ab, KU, Bb, KU, 16, t);
    for (int c = 0; c < 16; c++) {
        if (c + 1 < 16) cpwait1(); else cpwait0();
        __syncthreads();
        if (c + 2 < 16) issue3(sb, (c + 2) % 3, Ab, KU, Bb, KU, (c + 2) * 16, t);
        compute_chunk(aBase, bBase, (uint32_t)(c % 3) * STAGE_B, acc);
    }

    #pragma unroll
    for (int i = 0; i < 4; i++) {
        int R0 = n0 + wy * 64 + i * 16 + g;
        int R1 = R0 + 8;
        #pragma unroll
        for (int j = 0; j < 4; j++) {
            int C = j0 + wx * 32 + j * 8 + 2 * tg;
            float2 s = *(const float2*)&ws[C];
            ot[(size_t)R0 * KG + (C >> 1)] = pk(acc[i][j][0] * s.x, acc[i][j][1] * s.y);
            ot[(size_t)R1 * KG + (C >> 1)] = pk(acc[i][j][2] * s.x, acc[i][j][3] * s.y);
        }
    }
}

// ---------------- unified message+self GEMM ----------------
__global__ void __launch_bounds__(256)
gemm_msg(const uint32_t* __restrict__ Ag, const uint32_t* __restrict__ Xh,
         const uint32_t* __restrict__ Bg, const uint32_t* __restrict__ Wse,
         const float* __restrict__ bias,
         float* __restrict__ out, uint32_t* __restrict__ outH, int M) {
    int z = blockIdx.z;
    Ag += (size_t)z * M * KG;
    Xh += (size_t)z * M * KU;
    Bg += (size_t)z * DDIM * KG;
    if (out)  out  += (size_t)z * M * DDIM;
    if (outH) outH += (size_t)z * M * KU;

    extern __shared__ uint32_t smd[];
    uint32_t sb = smem_u32(smd);
    int t = threadIdx.x;
    int c0 = blockIdx.x * 128, r0 = blockIdx.y * 128;
    const uint32_t* Ab1 = Ag + (size_t)r0 * KG;
    const uint32_t* Ab2 = Xh + (size_t)r0 * KU;
    const uint32_t* Bb1 = Bg + (size_t)c0 * KG;
    const uint32_t* Bb2 = Wse + (size_t)c0 * KU;

    int lane = t & 31, g = lane >> 2, tg = lane & 3;
    int wid = t >> 5, wy = wid & 1, wx = wid >> 1;
    uint32_t aBase = sb + (uint32_t)(((wy * 64 + (lane & 15)) * RSH + (lane >> 4) * 4) * 4);
    uint32_t bBase = sb + 10240u +
                     (uint32_t)(((wx * 32 + (lane & 15)) * RSH + (lane >> 4) * 4) * 4);

    float acc[4][4][4];
    #pragma unroll
    for (int i = 0; i < 4; i++)
        #pragma unroll
        for (int j = 0; j < 4; j++)
            #pragma unroll
            for (int k = 0; k < 4; k++) acc[i][j][k] = 0.0f;

    const int nch = 36;  // 20 graph chunks + 16 feature chunks
    issue3(sb, 0, Ab1, KG, Bb1, KG, 0, t);
    issue3(sb, 1, Ab1, KG, Bb1, KG, 16, t);
    for (int c = 0; c < nch; c++) {
        if (c + 1 < nch) cpwait1(); else cpwait0();
        __syncthreads();
        if (c + 2 < nch) {
            int kkU = (c + 2) * 16;
            if (kkU < KG) issue3(sb, (c + 2) % 3, Ab1, KG, Bb1, KG, kkU, t);
            else          issue3(sb, (c + 2) % 3, Ab2, KU, Bb2, KU, kkU - KG, t);
        }
        compute_chunk(aBase, bBase, (uint32_t)(c % 3) * STAGE_B, acc);
    }

    #pragma unroll
    for (int i = 0; i < 4; i++) {
        int R0 = r0 + wy * 64 + i * 16 + g;
        int R1 = R0 + 8;
        #pragma unroll
        for (int j = 0; j < 4; j++) {
            int C = c0 + wx * 32 + j * 8 + 2 * tg;
            float2 bz = *(const float2*)&bias[C];
            float2 v0, v1;
            v0.x = fmaxf(acc[i][j][0] + bz.x, 0.0f);
            v0.y = fmaxf(acc[i][j][1] + bz.y, 0.0f);
            v1.x = fmaxf(acc[i][j][2] + bz.x, 0.0f);
            v1.y = fmaxf(acc[i][j][3] + bz.y, 0.0f);
            if (out) {
                *(float2*)&out[(size_t)R0 * DDIM + C] = v0;
                *(float2*)&out[(size_t)R1 * DDIM + C] = v1;
            }
            if (outH) {
                outH[(size_t)R0 * KU + (C >> 1)] = pk(v0.x, v0.y);
                outH[(size_t)R1 * KU + (C >> 1)] = pk(v1.x, v1.y);
            }
        }
    }
}

// ---------------- host orchestration ----------------
extern "C" void kernel_launch(void* const* d_in, const int* in_sizes, int n_in,
                              void* d_out_, int out_size) {
    const float* d_node = (const float*)d_in[0];
    const float* q_node = (const float*)d_in[1];
    const int*   qq     = (const int*)d_in[2];
    const int*   dq     = (const int*)d_in[3];
    const int*   dd     = (const int*)d_in[4];
    const int*   qd     = (const int*)d_in[5];
    const float* W_nw   = (const float*)d_in[6];
    const float* b_nw   = (const float*)d_in[7];
    const float* W_self = (const float*)d_in[8];
    const float* b_self = (const float*)d_in[9];
    const float* W_dd   = (const float*)d_in[10];
    const float* W_qq   = (const float*)d_in[11];
    const float* W_dq   = (const float*)d_in[12];
    const float* W_qd   = (const float*)d_in[13];

    float* out = (float*)d_out_;
    float* out_dnode = out;
    float* out_qnode = out + (size_t)BB * LDN * DDIM;
    float* out_dw    = out_qnode + (size_t)BB * LQN * DDIM;
    float* out_qw    = out_dw + (size_t)BB * 2 * LDN;

    float *p_dw, *p_qw;
    uint32_t *p_xdh, *p_xqh, *p_xdh2, *p_xqh2, *p_adh, *p_aqh, *p_bdh, *p_bqh, *p_wh;
    cudaGetSymbolAddress((void**)&p_dw, g_dw);
    cudaGetSymbolAddress((void**)&p_qw, g_qw);
    cudaGetSymbolAddress((void**)&p_xdh, g_xdh);
    cudaGetSymbolAddress((void**)&p_xqh, g_xqh);
    cudaGetSymbolAddress((void**)&p_xdh2, g_xdh2);
    cudaGetSymbolAddress((void**)&p_xqh2, g_xqh2);
    cudaGetSymbolAddress((void**)&p_adh, g_adh);
    cudaGetSymbolAddress((void**)&p_aqh, g_aqh);
    cudaGetSymbolAddress((void**)&p_bdh, g_bdh);
    cudaGetSymbolAddress((void**)&p_bqh, g_bqh);
    cudaGetSymbolAddress((void**)&p_wh, g_wh);

    cudaFuncSetAttribute(gemm_infoT, cudaFuncAttributeMaxDynamicSharedMemorySize, SMEM_DYN);
    cudaFuncSetAttribute(gemm_msg,   cudaFuncAttributeMaxDynamicSharedMemorySize, SMEM_DYN);

    const uint32_t* wh_self = p_wh;
    const uint32_t* wh_dd   = p_wh + 1 * (size_t)DDIM * KU;
    const uint32_t* wh_qd   = p_wh + 2 * (size_t)DDIM * KU;
    const uint32_t* wh_qq   = p_wh + 3 * (size_t)DDIM * KU;
    const uint32_t* wh_dq   = p_wh + 4 * (size_t)DDIM * KU;

    // one-time conversions (3 launches)
    cvt_w<<<320, 256>>>(W_self, W_dd, W_qd, W_qq, W_dq, p_wh);
    nbcvt2<<<(BB * LDN + BB * LQN) / 8, 256>>>(dd, dq, qq, qd, p_adh, p_aqh);
    cvt2<<<2048, 256>>>(d_node, q_node, p_xdh, p_xqh);

    uint32_t* xd = p_xdh;
    uint32_t* xq = p_xqh;
    uint32_t* xd_next = p_xdh2;
    uint32_t* xq_next = p_xqh2;

    for (int t = 0; t < 2; t++) {
        bool last = (t == 1);

        nw_h<<<BB * LDN / 8, 256>>>(xd, W_nw, b_nw, p_dw, out_dw + t * LDN,
                                    BB * LDN, LDN, 2 * LDN);
        nw_h<<<BB * LQN / 8, 256>>>(xq, W_nw, b_nw, p_qw, out_qw + t * LQN,
                                    BB * LQN, LQN, 2 * LQN);

        gemm_infoT<<<dim3(8, 4, BB), 256, SMEM_DYN>>>(wh_dd, wh_qd, xd, LDN, p_dw,
                                                      p_bdh, 0, p_bqh, 64);
        gemm_infoT<<<dim3(2, 4, BB), 256, SMEM_DYN>>>(wh_qq, wh_dq, xq, LQN, p_qw,
                                                      p_bqh, 0, p_bdh, 256);

        gemm_msg<<<dim3(4, LDN / 128, BB), 256, SMEM_DYN>>>(
            p_adh, xd, p_bdh, wh_self, b_self,
            last ? out_dnode : nullptr, last ? nullptr : xd_next, LDN);
        gemm_msg<<<dim3(4, LQN / 128, BB), 256, SMEM_DYN>>>(
            p_aqh, xq, p_bqh, wh_self, b_self,
            last ? out_qnode : nullptr, last ? nullptr : xq_next, LQN);

        uint32_t* tmp;
        tmp = xd; xd = xd_next; xd_next = tmp;
        tmp = xq; xq = xq_next; xq_next = tmp;
    }
    (void)in_sizes; (void)n_in; (void)out_size;
}